// round 1
// baseline (speedup 1.0000x reference)
#include <cuda_runtime.h>

#define BB   2
#define AA   512
#define TT   512
#define NF   128
#define NRBF 25
#define TTILE 64
#define NTILES (TT / TTILE)

// y = x @ Win, staged here between the two kernels (512 KB, static device array)
__device__ float g_y[BB * AA * NF];

__device__ __forceinline__ float ssp(float v) {
    // shifted softplus: logaddexp(v,0) - log(2), numerically stable
    return fmaxf(v, 0.0f) + __logf(1.0f + __expf(-fabsf(v))) - 0.69314718056f;
}

// ---------------------------------------------------------------------------
// Kernel 1: y[b,a,f] = sum_i x[b,a,i] * Win[i,f]   (tiny: 34 MFLOP)
// ---------------------------------------------------------------------------
__global__ void in2f_kernel(const float* __restrict__ x,
                            const float* __restrict__ Win) {
    const int row = blockIdx.x;          // b*AA + a
    __shared__ float xs[NF];
    const int f = threadIdx.x;
    xs[f] = x[row * NF + f];
    __syncthreads();
    float acc = 0.0f;
#pragma unroll 8
    for (int i = 0; i < NF; ++i) acc += xs[i] * Win[i * NF + f];
    g_y[row * NF + f] = acc;
}

// ---------------------------------------------------------------------------
// Kernel 2: fused filter-net + gather + triple product + reduce + f2out
// one block per (a, b); 256 threads
// ---------------------------------------------------------------------------

// smem layout (floats)
#define OFF_WF2  0                      // 128*128 = 16384
#define OFF_HT   16384                  // 128*64  =  8192  (H^T: [g][t])
#define OFF_WF1  24576                  // 25*128  =  3200
#define OFF_B1   27776                  // 128
#define OFF_B2   27904                  // 128
#define OFF_RED  28032                  // 8*128   =  1024
#define OFF_RBF  29056                  // 64*27   =  1728  (padded stride 27)
#define OFF_MASK 30784                  // 64
#define OFF_NJ   30848                  // 64 (int)
#define OFF_NK   30912                  // 64 (int)
#define SMEM_FLOATS 30976               // 123,904 bytes

__global__ __launch_bounds__(256, 1)
void cfconv_kernel(const float* __restrict__ r_ij,
                   const float* __restrict__ pmask,
                   const float* __restrict__ Wf1, const float* __restrict__ bf1,
                   const float* __restrict__ Wf2, const float* __restrict__ bf2,
                   const float* __restrict__ Wout, const float* __restrict__ bout,
                   const int* __restrict__ nj, const int* __restrict__ nk,
                   float* __restrict__ out) {
    extern __shared__ float sm[];
    float* sWf2 = sm + OFF_WF2;
    float* sHt  = sm + OFF_HT;
    float* sWf1 = sm + OFF_WF1;
    float* sB1  = sm + OFF_B1;
    float* sB2  = sm + OFF_B2;
    float* sRed = sm + OFF_RED;
    float* sRbf = sm + OFF_RBF;
    float* sMask= sm + OFF_MASK;
    int*   sNj  = (int*)(sm + OFF_NJ);
    int*   sNk  = (int*)(sm + OFF_NK);

    const int tid = threadIdx.x;
    const int a = blockIdx.x;
    const int b = blockIdx.y;
    const int ba = b * AA + a;
    const float* Yb = g_y + b * AA * NF;

    // one-time loads: Wf2 (64KB), Wf1 (12.5KB), biases
    for (int i = tid; i < NF * NF; i += 256) sWf2[i] = Wf2[i];
    for (int i = tid; i < NRBF * NF; i += 256) sWf1[i] = Wf1[i];
    if (tid < NF) { sB1[tid] = bf1[tid]; sB2[tid] = bf2[tid]; }

    // thread tiling for GEMM2: 8 t-rows x 4 f-cols per thread
    const int fq = tid & 31;        // f0 = fq*4   (covers all 128 f)
    const int tq = tid >> 5;        // t0 = tq*8   (covers 64 t of the tile)
    const int f0 = fq * 4;
    const int t0 = tq * 8;

    float facc0 = 0.f, facc1 = 0.f, facc2 = 0.f, facc3 = 0.f;

    for (int tile = 0; tile < NTILES; ++tile) {
        const int tbase = tile * TTILE;

        // ---- stage tile inputs ----
        const float* rsrc = r_ij + ((long)ba * TT + tbase) * NRBF;
        for (int i = tid; i < TTILE * NRBF; i += 256) {
            sRbf[(i / NRBF) * 27 + (i % NRBF)] = rsrc[i];
        }
        if (tid < TTILE) {
            const long p = (long)ba * TT + tbase + tid;
            sNj[tid] = nj[p];
            sNk[tid] = nk[p];
            sMask[tid] = pmask[p];
        }
        __syncthreads();

        // ---- GEMM1 + ssp -> H^T[g][t] ----
        {
            const int t = tid & 63;
            const int gq4 = tid >> 6;               // 0..3 -> g in [gq4*32, +32)
            float rr[NRBF];
#pragma unroll
            for (int r = 0; r < NRBF; ++r) rr[r] = sRbf[t * 27 + r];
#pragma unroll
            for (int gi = 0; gi < 8; ++gi) {
                const int g0 = gq4 * 32 + gi * 4;
                float4 acc = *(const float4*)(sB1 + g0);
#pragma unroll
                for (int r = 0; r < NRBF; ++r) {
                    const float4 w = *(const float4*)(sWf1 + r * NF + g0);
                    acc.x += rr[r] * w.x;
                    acc.y += rr[r] * w.y;
                    acc.z += rr[r] * w.z;
                    acc.w += rr[r] * w.w;
                }
                sHt[(g0 + 0) * TTILE + t] = ssp(acc.x);
                sHt[(g0 + 1) * TTILE + t] = ssp(acc.y);
                sHt[(g0 + 2) * TTILE + t] = ssp(acc.z);
                sHt[(g0 + 3) * TTILE + t] = ssp(acc.w);
            }
        }
        __syncthreads();

        // ---- GEMM2 (register-blocked 8t x 4f) ----
        float wacc[8][4];
#pragma unroll
        for (int i = 0; i < 8; ++i)
#pragma unroll
            for (int j = 0; j < 4; ++j) wacc[i][j] = 0.0f;

#pragma unroll 4
        for (int g = 0; g < NF; ++g) {
            const float4 w  = *(const float4*)(sWf2 + g * NF + f0);
            const float4 h0 = *(const float4*)(sHt + g * TTILE + t0);
            const float4 h1 = *(const float4*)(sHt + g * TTILE + t0 + 4);
            const float hh[8] = {h0.x, h0.y, h0.z, h0.w, h1.x, h1.y, h1.z, h1.w};
#pragma unroll
            for (int i = 0; i < 8; ++i) {
                wacc[i][0] += hh[i] * w.x;
                wacc[i][1] += hh[i] * w.y;
                wacc[i][2] += hh[i] * w.z;
                wacc[i][3] += hh[i] * w.w;
            }
        }

        // ---- gather y_j, y_k (L2-resident) + masked accumulate over t ----
        {
            const float4 b2v = *(const float4*)(sB2 + f0);
#pragma unroll
            for (int i = 0; i < 8; ++i) {
                const int t = t0 + i;
                const float m = sMask[t];
                const float4 yj = *(const float4*)(Yb + sNj[t] * NF + f0);
                const float4 yk = *(const float4*)(Yb + sNk[t] * NF + f0);
                facc0 += (wacc[i][0] + b2v.x) * yj.x * yk.x * m;
                facc1 += (wacc[i][1] + b2v.y) * yj.y * yk.y * m;
                facc2 += (wacc[i][2] + b2v.z) * yj.z * yk.z * m;
                facc3 += (wacc[i][3] + b2v.w) * yj.w * yk.w * m;
            }
        }
        __syncthreads();
    }

    // ---- reduce partial sums across the 8 tq groups ----
    {
        float4 v = make_float4(facc0, facc1, facc2, facc3);
        *(float4*)(sRed + tq * NF + f0) = v;
    }
    __syncthreads();
    if (tid < NF) {
        float tot = 0.0f;
#pragma unroll
        for (int q = 0; q < 8; ++q) tot += sRed[q * NF + tid];
        sRed[tid] = tot;                 // row 0 = total y[b,a,:]
    }
    __syncthreads();

    // ---- epilogue: out = ssp(y @ Wout + bout) ----
    {
        const int o = tid & 127;
        const int half = tid >> 7;       // split the f-reduction over 2 groups
        float acc = 0.0f;
        const float* Wp = Wout + half * 64 * NF + o;
#pragma unroll 8
        for (int f = 0; f < 64; ++f) acc += sRed[half * 64 + f] * Wp[f * NF];
        sRed[NF + half * NF + o] = acc;  // rows 1 and 2 as scratch
    }
    __syncthreads();
    if (tid < NF) {
        const float v = sRed[NF + tid] + sRed[2 * NF + tid] + bout[tid];
        out[(long)ba * NF + tid] = ssp(v);
    }
}

// ---------------------------------------------------------------------------
extern "C" void kernel_launch(void* const* d_in, const int* in_sizes, int n_in,
                              void* d_out, int out_size) {
    const float* x    = (const float*)d_in[0];
    const float* r_ij = (const float*)d_in[1];
    const float* mask = (const float*)d_in[2];
    const float* Wf1  = (const float*)d_in[3];
    const float* bf1  = (const float*)d_in[4];
    const float* Wf2  = (const float*)d_in[5];
    const float* bf2  = (const float*)d_in[6];
    const float* Win  = (const float*)d_in[7];
    const float* Wout = (const float*)d_in[8];
    const float* bout = (const float*)d_in[9];
    const int*   nj   = (const int*)d_in[10];
    const int*   nk   = (const int*)d_in[11];
    float* out = (float*)d_out;

    in2f_kernel<<<BB * AA, NF>>>(x, Win);

    const int smem_bytes = SMEM_FLOATS * (int)sizeof(float);
    cudaFuncSetAttribute(cfconv_kernel,
                         cudaFuncAttributeMaxDynamicSharedMemorySize, smem_bytes);
    dim3 grid(AA, BB);
    cfconv_kernel<<<grid, 256, smem_bytes>>>(r_ij, mask, Wf1, bf1, Wf2, bf2,
                                             Wout, bout, nj, nk, out);
}

// round 3
// speedup vs baseline: 2.1332x; 2.1332x over previous
#include <cuda_runtime.h>
#include <cstdint>

#define BB   2
#define AA   512
#define TT   512
#define NF   128
#define NRBF 25
#define TILT 128
#define NTIL (TT / TILT)

#define RS 36     // sRbf row stride (floats): 32 + 4 pad -> conflict-free frag loads
#define HS 132    // sH   row stride (floats): 128 + 4 pad

__device__ float g_y[BB * AA * NF];

__device__ __forceinline__ float ssp(float v) {
    return fmaxf(v, 0.0f) + __logf(1.0f + __expf(-fabsf(v))) - 0.69314718056f;
}
__device__ __forceinline__ uint32_t to_tf32(float v) {
    uint32_t r;
    asm("cvt.rna.tf32.f32 %0, %1;" : "=r"(r) : "f"(v));
    return r;
}
// m16n8k8 tf32 MMA (sm_80+ baseline PTX -> compiles for compute_103)
__device__ __forceinline__ void mma8(float* c, const uint32_t* a,
                                     uint32_t b0, uint32_t b1) {
    asm volatile(
        "mma.sync.aligned.m16n8k8.row.col.f32.tf32.tf32.f32 "
        "{%0,%1,%2,%3}, {%4,%5,%6,%7}, {%8,%9}, {%0,%1,%2,%3};"
        : "+f"(c[0]), "+f"(c[1]), "+f"(c[2]), "+f"(c[3])
        : "r"(a[0]), "r"(a[1]), "r"(a[2]), "r"(a[3]), "r"(b0), "r"(b1));
}

// ---------------------------------------------------------------------------
// Kernel 1: y = x @ Win
// ---------------------------------------------------------------------------
__global__ void in2f_kernel(const float* __restrict__ x,
                            const float* __restrict__ Win) {
    const int row = blockIdx.x;
    __shared__ float xs[NF];
    const int f = threadIdx.x;
    xs[f] = x[row * NF + f];
    __syncthreads();
    float acc = 0.0f;
#pragma unroll 8
    for (int i = 0; i < NF; ++i) acc += xs[i] * Win[i * NF + f];
    g_y[row * NF + f] = acc;
}

// ---------------------------------------------------------------------------
// SMEM layout (byte offsets)
// ---------------------------------------------------------------------------
#define OFF_H     0          // 128*132*4 = 67584 (H, tf32 bits)
#define OFF_W2P   67584      // 16*32*32*4 = 65536 (Wf2 B-fragment permuted)
#define OFF_RBF   133120     // 128*36*4 = 18432 (rbf, tf32 bits, zero-padded K)
#define OFF_W1P   151552     // 4*32*32*4 = 16384 (Wf1 B-fragment permuted)
#define OFF_BF1   167936     // 512
#define OFF_BF2   168448     // 512
#define OFF_MASK  168960     // 512
#define OFF_NJ    169472     // 512
#define OFF_NK    169984     // 512
#define OFF_PART  170496     // 8*128*4 = 4096
#define OFF_Y     174592     // 512
#define OFF_RED   175104     // 1024
#define SMEM_BYTES 176128

__global__ __launch_bounds__(256, 1)
void cfconv_mma(const float* __restrict__ r_ij,
                const float* __restrict__ pmask,
                const float* __restrict__ Wf1, const float* __restrict__ bf1,
                const float* __restrict__ Wf2, const float* __restrict__ bf2,
                const float* __restrict__ Wout, const float* __restrict__ bout,
                const int* __restrict__ nj, const int* __restrict__ nk,
                float* __restrict__ out) {
    extern __shared__ __align__(16) char smem[];
    uint32_t* sRbf = (uint32_t*)(smem + OFF_RBF);
    uint32_t* sH   = (uint32_t*)(smem + OFF_H);
    float* sW1p  = (float*)(smem + OFF_W1P);
    float* sW2p  = (float*)(smem + OFF_W2P);
    float* sBf1  = (float*)(smem + OFF_BF1);
    float* sBf2  = (float*)(smem + OFF_BF2);
    float* sMask = (float*)(smem + OFF_MASK);
    int*   sNj   = (int*)(smem + OFF_NJ);
    int*   sNk   = (int*)(smem + OFF_NK);
    float* sPart = (float*)(smem + OFF_PART);
    float* sY    = (float*)(smem + OFF_Y);
    float* sRed  = (float*)(smem + OFF_RED);

    const int tid  = threadIdx.x;
    const int wid  = tid >> 5;
    const int lane = tid & 31;
    const int gid  = lane >> 2;      // group id (row within frag)
    const int l4   = lane & 3;       // thread-in-group (col within frag)
    const int m0   = wid * 16;       // this warp's t-row base
    const int a = blockIdx.x, b = blockIdx.y;
    const int ba = b * AA + a;
    const float* Yb = g_y + b * AA * NF;

    // ---- prologue: zero rbf K-padding, biases, permuted B-frag tables ----
    for (int i = tid; i < 128 * RS; i += 256) sRbf[i] = 0u;
    if (tid < NF) { sBf1[tid] = bf1[tid]; sBf2[tid] = bf2[tid]; }
    for (int idx = tid; idx < 4 * 32 * 32; idx += 256) {
        const int ks = idx >> 10, ln = (idx >> 5) & 31, i = idx & 31;
        const int r = ks * 8 + (ln & 3) + ((i & 1) << 2);
        const int f = ((i >> 1) << 3) + (ln >> 2);
        const float v = (r < NRBF) ? Wf1[r * NF + f] : 0.0f;
        const uint32_t off = (uint32_t)((ks * 32 + ln) * 32 +
                                        ((((i >> 2) ^ (ln & 7)) << 2) + (i & 3)));
        sW1p[off] = __uint_as_float(to_tf32(v));
    }
    for (int idx = tid; idx < 16 * 32 * 32; idx += 256) {
        const int ks = idx >> 10, ln = (idx >> 5) & 31, i = idx & 31;
        const int g = ks * 8 + (ln & 3) + ((i & 1) << 2);
        const int f = ((i >> 1) << 3) + (ln >> 2);
        const uint32_t off = (uint32_t)((ks * 32 + ln) * 32 +
                                        ((((i >> 2) ^ (ln & 7)) << 2) + (i & 3)));
        sW2p[off] = __uint_as_float(to_tf32(Wf2[g * NF + f]));
    }
    __syncthreads();

    float acc[32];
#pragma unroll
    for (int i = 0; i < 32; ++i) acc[i] = 0.0f;

    for (int tile = 0; tile < NTIL; ++tile) {
        const int tbase = tile * TILT;

        // ---- stage tile inputs ----
        const float* rsrc = r_ij + ((long)ba * TT + tbase) * NRBF;
        for (int i = tid; i < TILT * NRBF; i += 256) {
            const int t = i / NRBF, r = i - t * NRBF;
            sRbf[t * RS + r] = to_tf32(rsrc[i]);
        }
        if (tid < TILT) {
            const long p = (long)ba * TT + tbase + tid;
            sMask[tid] = pmask[p];
            sNj[tid] = nj[p];
            sNk[tid] = nk[p];
        }
        __syncthreads();

        float C[64];
#pragma unroll
        for (int i = 0; i < 64; ++i) C[i] = 0.0f;

        // ---- GEMM1: H = rbf @ Wf1  (K=32 incl. zero pad, 4 k-steps) ----
#pragma unroll
        for (int ks = 0; ks < 4; ++ks) {
            uint32_t afr[4];
            const int r0 = ks * 8 + l4;
            afr[0] = sRbf[(m0 + gid) * RS + r0];
            afr[1] = sRbf[(m0 + gid + 8) * RS + r0];
            afr[2] = sRbf[(m0 + gid) * RS + r0 + 4];
            afr[3] = sRbf[(m0 + gid + 8) * RS + r0 + 4];
            float4 bf[8];
            const float4* rowp = (const float4*)(sW1p + (ks * 32 + lane) * 32);
#pragma unroll
            for (int gq = 0; gq < 8; ++gq) bf[gq] = rowp[gq ^ (lane & 7)];
            const uint32_t* bu = (const uint32_t*)bf;
#pragma unroll
            for (int nt = 0; nt < 16; ++nt)
                mma8(C + nt * 4, afr, bu[2 * nt], bu[2 * nt + 1]);
        }

        // ---- ssp(C + bf1) -> sH (tf32 bits, padded layout) ----
#pragma unroll
        for (int nt = 0; nt < 16; ++nt) {
            const int f0 = nt * 8 + l4 * 2;
            const float2 b1v = *(const float2*)(sBf1 + f0);
            const uint32_t h0 = to_tf32(ssp(C[nt * 4 + 0] + b1v.x));
            const uint32_t h1 = to_tf32(ssp(C[nt * 4 + 1] + b1v.y));
            const uint32_t h2 = to_tf32(ssp(C[nt * 4 + 2] + b1v.x));
            const uint32_t h3 = to_tf32(ssp(C[nt * 4 + 3] + b1v.y));
            *(uint2*)(sH + (m0 + gid) * HS + f0)     = make_uint2(h0, h1);
            *(uint2*)(sH + (m0 + gid + 8) * HS + f0) = make_uint2(h2, h3);
        }
        __syncthreads();

        // ---- GEMM2: W = H @ Wf2  (K=128, 16 k-steps) ----
#pragma unroll
        for (int i = 0; i < 64; ++i) C[i] = 0.0f;
#pragma unroll
        for (int ks = 0; ks < 16; ++ks) {
            uint32_t afr[4];
            const int g0 = ks * 8 + l4;
            afr[0] = sH[(m0 + gid) * HS + g0];
            afr[1] = sH[(m0 + gid + 8) * HS + g0];
            afr[2] = sH[(m0 + gid) * HS + g0 + 4];
            afr[3] = sH[(m0 + gid + 8) * HS + g0 + 4];
            float4 bf[8];
            const float4* rowp = (const float4*)(sW2p + (ks * 32 + lane) * 32);
#pragma unroll
            for (int gq = 0; gq < 8; ++gq) bf[gq] = rowp[gq ^ (lane & 7)];
            const uint32_t* bu = (const uint32_t*)bf;
#pragma unroll
            for (int nt = 0; nt < 16; ++nt)
                mma8(C + nt * 4, afr, bu[2 * nt], bu[2 * nt + 1]);
        }

        // ---- epilogue: acc_f += (W + bf2) * yj * yk * mask over this tile ----
        {
            const int t0 = m0 + gid, t1 = t0 + 8;
            const float mk0 = sMask[t0], mk1 = sMask[t1];
            const float* yj0 = Yb + sNj[t0] * NF;
            const float* yk0 = Yb + sNk[t0] * NF;
            const float* yj1 = Yb + sNj[t1] * NF;
            const float* yk1 = Yb + sNk[t1] * NF;
#pragma unroll
            for (int nt = 0; nt < 16; ++nt) {
                const int f0 = nt * 8 + l4 * 2;
                const float2 b2 = *(const float2*)(sBf2 + f0);
                const float2 j0 = *(const float2*)(yj0 + f0);
                const float2 k0 = *(const float2*)(yk0 + f0);
                const float2 j1 = *(const float2*)(yj1 + f0);
                const float2 k1 = *(const float2*)(yk1 + f0);
                const float p0x = mk0 * j0.x * k0.x, p0y = mk0 * j0.y * k0.y;
                const float p1x = mk1 * j1.x * k1.x, p1y = mk1 * j1.y * k1.y;
                acc[2 * nt]     += (C[nt * 4 + 0] + b2.x) * p0x
                                 + (C[nt * 4 + 2] + b2.x) * p1x;
                acc[2 * nt + 1] += (C[nt * 4 + 1] + b2.y) * p0y
                                 + (C[nt * 4 + 3] + b2.y) * p1y;
            }
        }
        __syncthreads();
    }

    // ---- reduce acc over gid (lanes differing in bits 2..4) ----
#pragma unroll
    for (int s = 4; s < 32; s <<= 1) {
#pragma unroll
        for (int i = 0; i < 32; ++i)
            acc[i] += __shfl_xor_sync(0xffffffffu, acc[i], s);
    }
    if (lane < 4) {
#pragma unroll
        for (int nt = 0; nt < 16; ++nt) {
            sPart[wid * NF + nt * 8 + lane * 2]     = acc[2 * nt];
            sPart[wid * NF + nt * 8 + lane * 2 + 1] = acc[2 * nt + 1];
        }
    }
    __syncthreads();
    if (tid < NF) {
        float s = 0.0f;
#pragma unroll
        for (int w = 0; w < 8; ++w) s += sPart[w * NF + tid];
        sY[tid] = s;
    }
    __syncthreads();

    // ---- f2out: out = ssp(y @ Wout + bout) ----
    {
        const int o = tid & 127;
        const int half = tid >> 7;
        float s = 0.0f;
        const float* Wp = Wout + half * 64 * NF + o;
#pragma unroll 8
        for (int f = 0; f < 64; ++f) s += sY[half * 64 + f] * Wp[f * NF];
        sRed[half * NF + o] = s;
    }
    __syncthreads();
    if (tid < NF)
        out[(long)ba * NF + tid] = ssp(sRed[tid] + sRed[NF + tid] + bout[tid]);
}

// ---------------------------------------------------------------------------
extern "C" void kernel_launch(void* const* d_in, const int* in_sizes, int n_in,
                              void* d_out, int out_size) {
    const float* x    = (const float*)d_in[0];
    const float* r_ij = (const float*)d_in[1];
    const float* mask = (const float*)d_in[2];
    const float* Wf1  = (const float*)d_in[3];
    const float* bf1  = (const float*)d_in[4];
    const float* Wf2  = (const float*)d_in[5];
    const float* bf2  = (const float*)d_in[6];
    const float* Win  = (const float*)d_in[7];
    const float* Wout = (const float*)d_in[8];
    const float* bout = (const float*)d_in[9];
    const int*   nj   = (const int*)d_in[10];
    const int*   nk   = (const int*)d_in[11];
    float* out = (float*)d_out;

    in2f_kernel<<<BB * AA, NF>>>(x, Win);

    cudaFuncSetAttribute(cfconv_mma,
                         cudaFuncAttributeMaxDynamicSharedMemorySize, SMEM_BYTES);
    dim3 grid(AA, BB);
    cfconv_mma<<<grid, 256, SMEM_BYTES>>>(r_ij, mask, Wf1, bf1, Wf2, bf2,
                                          Wout, bout, nj, nk, out);
}

// round 4
// speedup vs baseline: 2.3588x; 1.1058x over previous
#include <cuda_runtime.h>
#include <cstdint>

#define BB   2
#define AA   512
#define TT   512
#define NF   128
#define NRBF 25
#define TILT 128
#define NTIL (TT / TILT)

#define RS 36     // sRbf row stride (floats): 32 + 4 pad
#define HS 132    // sH   row stride (floats): 128 + 4 pad

__device__ float g_y[BB * AA * NF];

__device__ __forceinline__ float ssp(float v) {
    return fmaxf(v, 0.0f) + __logf(1.0f + __expf(-fabsf(v))) - 0.69314718056f;
}
__device__ __forceinline__ uint32_t to_tf32(float v) {
    uint32_t r;
    asm("cvt.rna.tf32.f32 %0, %1;" : "=r"(r) : "f"(v));
    return r;
}
__device__ __forceinline__ void mma8(float* c, const uint32_t* a,
                                     uint32_t b0, uint32_t b1) {
    asm volatile(
        "mma.sync.aligned.m16n8k8.row.col.f32.tf32.tf32.f32 "
        "{%0,%1,%2,%3}, {%4,%5,%6,%7}, {%8,%9}, {%0,%1,%2,%3};"
        : "+f"(c[0]), "+f"(c[1]), "+f"(c[2]), "+f"(c[3])
        : "r"(a[0]), "r"(a[1]), "r"(a[2]), "r"(a[3]), "r"(b0), "r"(b1));
}

// ---------------------------------------------------------------------------
__global__ void in2f_kernel(const float* __restrict__ x,
                            const float* __restrict__ Win) {
    const int row = blockIdx.x;
    __shared__ float xs[NF];
    const int f = threadIdx.x;
    xs[f] = x[row * NF + f];
    __syncthreads();
    float acc = 0.0f;
#pragma unroll 8
    for (int i = 0; i < NF; ++i) acc += xs[i] * Win[i * NF + f];
    g_y[row * NF + f] = acc;
}

// ---------------------------------------------------------------------------
// SMEM layout (byte offsets)
// ---------------------------------------------------------------------------
#define OFF_H     0          // 128*132*4 = 67584
#define OFF_W2P   67584      // 65536
#define OFF_RBF   133120     // 128*36*4 = 18432
#define OFF_W1P   151552     // 16384
#define OFF_BF1   167936     // 512
#define OFF_BF2   168448     // 512
#define OFF_MASK  168960     // 512
#define OFF_NJ    169472     // 512
#define OFF_NK    169984     // 512
#define OFF_PART  170496     // 4*128*4 = 2048
#define OFF_Y     172544     // 512
#define OFF_RED   173056     // 4*128*4 = 2048
#define SMEM_BYTES 175104

#define NTHREADS 512

__global__ __launch_bounds__(NTHREADS, 1)
void cfconv_mma(const float* __restrict__ r_ij,
                const float* __restrict__ pmask,
                const float* __restrict__ Wf1, const float* __restrict__ bf1,
                const float* __restrict__ Wf2, const float* __restrict__ bf2,
                const float* __restrict__ Wout, const float* __restrict__ bout,
                const int* __restrict__ nj, const int* __restrict__ nk,
                float* __restrict__ out) {
    extern __shared__ __align__(16) char smem[];
    uint32_t* sRbf = (uint32_t*)(smem + OFF_RBF);
    uint32_t* sH   = (uint32_t*)(smem + OFF_H);
    float* sW1p  = (float*)(smem + OFF_W1P);
    float* sW2p  = (float*)(smem + OFF_W2P);
    float* sBf1  = (float*)(smem + OFF_BF1);
    float* sBf2  = (float*)(smem + OFF_BF2);
    float* sMask = (float*)(smem + OFF_MASK);
    int*   sNj   = (int*)(smem + OFF_NJ);
    int*   sNk   = (int*)(smem + OFF_NK);
    float* sPart = (float*)(smem + OFF_PART);
    float* sY    = (float*)(smem + OFF_Y);
    float* sRed  = (float*)(smem + OFF_RED);

    const int tid  = threadIdx.x;
    const int wid  = tid >> 5;
    const int lane = tid & 31;
    const int gid  = lane >> 2;
    const int l4   = lane & 3;
    const int wm   = wid >> 2;          // warp m-row (0..3)
    const int wn   = wid & 3;           // warp n-col (0..3)
    const int mbase = wm * 32;
    const int nb4   = wn * 2;           // float4-group base in permuted B rows
    const int a = blockIdx.x, b = blockIdx.y;
    const int ba = b * AA + a;
    const float* Yb = g_y + b * AA * NF;

    // ---- prologue ----
    for (int i = tid; i < 128 * RS; i += NTHREADS) sRbf[i] = 0u;
    if (tid < NF) { sBf1[tid] = bf1[tid]; sBf2[tid] = bf2[tid]; }
    for (int idx = tid; idx < 4 * 32 * 32; idx += NTHREADS) {
        const int ks = idx >> 10, ln = (idx >> 5) & 31, i = idx & 31;
        const int r = ks * 8 + (ln & 3) + ((i & 1) << 2);
        const int f = ((i >> 1) << 3) + (ln >> 2);
        const float v = (r < NRBF) ? Wf1[r * NF + f] : 0.0f;
        const uint32_t off = (uint32_t)((ks * 32 + ln) * 32 +
                                        ((((i >> 2) ^ (ln & 7)) << 2) + (i & 3)));
        sW1p[off] = __uint_as_float(to_tf32(v));
    }
    for (int idx = tid; idx < 16 * 32 * 32; idx += NTHREADS) {
        const int ks = idx >> 10, ln = (idx >> 5) & 31, i = idx & 31;
        const int g = ks * 8 + (ln & 3) + ((i & 1) << 2);
        const int f = ((i >> 1) << 3) + (ln >> 2);
        const uint32_t off = (uint32_t)((ks * 32 + ln) * 32 +
                                        ((((i >> 2) ^ (ln & 7)) << 2) + (i & 3)));
        sW2p[off] = __uint_as_float(to_tf32(Wf2[g * NF + f]));
    }
    __syncthreads();

    float acc[4][2];
#pragma unroll
    for (int j = 0; j < 4; ++j) { acc[j][0] = 0.0f; acc[j][1] = 0.0f; }

    for (int tile = 0; tile < NTIL; ++tile) {
        const int tbase = tile * TILT;

        // ---- stage tile inputs ----
        const float* rsrc = r_ij + ((long)ba * TT + tbase) * NRBF;
        for (int i = tid; i < TILT * NRBF; i += NTHREADS) {
            const int t = i / NRBF, r = i - t * NRBF;
            sRbf[t * RS + r] = to_tf32(rsrc[i]);
        }
        if (tid < TILT) {
            const long p = (long)ba * TT + tbase + tid;
            sMask[tid] = pmask[p];
            sNj[tid] = nj[p];
            sNk[tid] = nk[p];
        }
        __syncthreads();

        float C[2][4][4];
#pragma unroll
        for (int mt = 0; mt < 2; ++mt)
#pragma unroll
            for (int j = 0; j < 4; ++j)
#pragma unroll
                for (int q = 0; q < 4; ++q) C[mt][j][q] = 0.0f;

        // ---- GEMM1: H = rbf @ Wf1 (K=32 padded, 4 k-steps) ----
#pragma unroll
        for (int ks = 0; ks < 4; ++ks) {
            uint32_t A[2][4];
#pragma unroll
            for (int mt = 0; mt < 2; ++mt) {
                const int r0 = mbase + mt * 16 + gid;
                const int c0 = ks * 8 + l4;
                A[mt][0] = sRbf[r0 * RS + c0];
                A[mt][1] = sRbf[(r0 + 8) * RS + c0];
                A[mt][2] = sRbf[r0 * RS + c0 + 4];
                A[mt][3] = sRbf[(r0 + 8) * RS + c0 + 4];
            }
            const float4* rowp = (const float4*)(sW1p + (ks * 32 + lane) * 32);
            float4 bq[2];
            bq[0] = rowp[nb4 ^ (lane & 7)];
            bq[1] = rowp[(nb4 + 1) ^ (lane & 7)];
            const uint32_t* bu = (const uint32_t*)bq;
#pragma unroll
            for (int mt = 0; mt < 2; ++mt)
#pragma unroll
                for (int j = 0; j < 4; ++j)
                    mma8(C[mt][j], A[mt], bu[2 * j], bu[2 * j + 1]);
        }

        // ---- ssp(C + bf1) -> sH ----
#pragma unroll
        for (int mt = 0; mt < 2; ++mt)
#pragma unroll
            for (int j = 0; j < 4; ++j) {
                const int f0 = wn * 32 + j * 8 + l4 * 2;
                const float2 b1v = *(const float2*)(sBf1 + f0);
                const int r0 = mbase + mt * 16 + gid;
                *(uint2*)(sH + r0 * HS + f0) =
                    make_uint2(to_tf32(ssp(C[mt][j][0] + b1v.x)),
                               to_tf32(ssp(C[mt][j][1] + b1v.y)));
                *(uint2*)(sH + (r0 + 8) * HS + f0) =
                    make_uint2(to_tf32(ssp(C[mt][j][2] + b1v.x)),
                               to_tf32(ssp(C[mt][j][3] + b1v.y)));
            }
        __syncthreads();

        // ---- GEMM2: W = H @ Wf2 (K=128, 16 k-steps) ----
#pragma unroll
        for (int mt = 0; mt < 2; ++mt)
#pragma unroll
            for (int j = 0; j < 4; ++j)
#pragma unroll
                for (int q = 0; q < 4; ++q) C[mt][j][q] = 0.0f;
#pragma unroll
        for (int ks = 0; ks < 16; ++ks) {
            uint32_t A[2][4];
#pragma unroll
            for (int mt = 0; mt < 2; ++mt) {
                const int r0 = mbase + mt * 16 + gid;
                const int c0 = ks * 8 + l4;
                A[mt][0] = sH[r0 * HS + c0];
                A[mt][1] = sH[(r0 + 8) * HS + c0];
                A[mt][2] = sH[r0 * HS + c0 + 4];
                A[mt][3] = sH[(r0 + 8) * HS + c0 + 4];
            }
            const float4* rowp = (const float4*)(sW2p + (ks * 32 + lane) * 32);
            float4 bq[2];
            bq[0] = rowp[nb4 ^ (lane & 7)];
            bq[1] = rowp[(nb4 + 1) ^ (lane & 7)];
            const uint32_t* bu = (const uint32_t*)bq;
#pragma unroll
            for (int mt = 0; mt < 2; ++mt)
#pragma unroll
                for (int j = 0; j < 4; ++j)
                    mma8(C[mt][j], A[mt], bu[2 * j], bu[2 * j + 1]);
        }

        // ---- epilogue: acc += (W + bf2) * yj * yk * mask ----
#pragma unroll
        for (int mt = 0; mt < 2; ++mt)
#pragma unroll
            for (int rr = 0; rr < 2; ++rr) {
                const int t = mbase + mt * 16 + gid + rr * 8;
                const float mk = sMask[t];
                const float* yjp = Yb + sNj[t] * NF;
                const float* ykp = Yb + sNk[t] * NF;
#pragma unroll
                for (int j = 0; j < 4; ++j) {
                    const int f0 = wn * 32 + j * 8 + l4 * 2;
                    const float2 b2 = *(const float2*)(sBf2 + f0);
                    const float2 j2 = *(const float2*)(yjp + f0);
                    const float2 k2 = *(const float2*)(ykp + f0);
                    acc[j][0] = fmaf((C[mt][j][rr * 2 + 0] + b2.x),
                                     mk * j2.x * k2.x, acc[j][0]);
                    acc[j][1] = fmaf((C[mt][j][rr * 2 + 1] + b2.y),
                                     mk * j2.y * k2.y, acc[j][1]);
                }
            }
        __syncthreads();
    }

    // ---- reduce over gid (lane strides 4,8,16) ----
#pragma unroll
    for (int s = 4; s < 32; s <<= 1) {
#pragma unroll
        for (int j = 0; j < 4; ++j) {
            acc[j][0] += __shfl_xor_sync(0xffffffffu, acc[j][0], s);
            acc[j][1] += __shfl_xor_sync(0xffffffffu, acc[j][1], s);
        }
    }
    if (lane < 4) {
#pragma unroll
        for (int j = 0; j < 4; ++j) {
            sPart[wm * NF + wn * 32 + j * 8 + lane * 2]     = acc[j][0];
            sPart[wm * NF + wn * 32 + j * 8 + lane * 2 + 1] = acc[j][1];
        }
    }
    __syncthreads();
    if (tid < NF) {
        sY[tid] = sPart[tid] + sPart[NF + tid] +
                  sPart[2 * NF + tid] + sPart[3 * NF + tid];
    }
    __syncthreads();

    // ---- f2out: out = ssp(y @ Wout + bout), 4-way split ----
    {
        const int o = tid & 127;
        const int q = tid >> 7;
        float s = 0.0f;
        const float* Wp = Wout + q * 32 * NF + o;
#pragma unroll 8
        for (int f = 0; f < 32; ++f) s += sY[q * 32 + f] * Wp[f * NF];
        sRed[q * NF + o] = s;
    }
    __syncthreads();
    if (tid < NF) {
        out[(long)ba * NF + tid] = ssp(sRed[tid] + sRed[NF + tid] +
                                       sRed[2 * NF + tid] + sRed[3 * NF + tid] +
                                       bout[tid]);
    }
}

// ---------------------------------------------------------------------------
extern "C" void kernel_launch(void* const* d_in, const int* in_sizes, int n_in,
                              void* d_out, int out_size) {
    const float* x    = (const float*)d_in[0];
    const float* r_ij = (const float*)d_in[1];
    const float* mask = (const float*)d_in[2];
    const float* Wf1  = (const float*)d_in[3];
    const float* bf1  = (const float*)d_in[4];
    const float* Wf2  = (const float*)d_in[5];
    const float* bf2  = (const float*)d_in[6];
    const float* Win  = (const float*)d_in[7];
    const float* Wout = (const float*)d_in[8];
    const float* bout = (const float*)d_in[9];
    const int*   nj   = (const int*)d_in[10];
    const int*   nk   = (const int*)d_in[11];
    float* out = (float*)d_out;

    in2f_kernel<<<BB * AA, NF>>>(x, Win);

    cudaFuncSetAttribute(cfconv_mma,
                         cudaFuncAttributeMaxDynamicSharedMemorySize, SMEM_BYTES);
    dim3 grid(AA, BB);
    cfconv_mma<<<grid, NTHREADS, SMEM_BYTES>>>(r_ij, mask, Wf1, bf1, Wf2, bf2,
                                               Wout, bout, nj, nk, out);
}

// round 5
// speedup vs baseline: 2.5162x; 1.0667x over previous
#include <cuda_runtime.h>
#include <cstdint>

#define BB   2
#define AA   512
#define TT   512
#define NF   128
#define NRBF 25
#define TILT 64
#define NTIL (TT / TILT)   // 8

#define RS 36     // sRbf row stride (floats)
#define HS 132    // sH   row stride (floats)

__device__ float g_y[BB * AA * NF];
__device__ float g_w1p[4 * 32 * 32];     // permuted tf32 Wf1 B-fragments
__device__ float g_w2p[16 * 32 * 32];    // permuted tf32 Wf2 B-fragments

__device__ __forceinline__ float ssp(float v) {
    return fmaxf(v, 0.0f) + __logf(1.0f + __expf(-fabsf(v))) - 0.69314718056f;
}
__device__ __forceinline__ uint32_t to_tf32(float v) {
    uint32_t r;
    asm("cvt.rna.tf32.f32 %0, %1;" : "=r"(r) : "f"(v));
    return r;
}
__device__ __forceinline__ void mma8(float* c, const uint32_t* a,
                                     uint32_t b0, uint32_t b1) {
    asm volatile(
        "mma.sync.aligned.m16n8k8.row.col.f32.tf32.tf32.f32 "
        "{%0,%1,%2,%3}, {%4,%5,%6,%7}, {%8,%9}, {%0,%1,%2,%3};"
        : "+f"(c[0]), "+f"(c[1]), "+f"(c[2]), "+f"(c[3])
        : "r"(a[0]), "r"(a[1]), "r"(a[2]), "r"(a[3]), "r"(b0), "r"(b1));
}

// ---------------------------------------------------------------------------
// prep: permuted tf32 B-fragment tables for Wf1 (pad K to 32) and Wf2
// ---------------------------------------------------------------------------
__global__ void prep_kernel(const float* __restrict__ Wf1,
                            const float* __restrict__ Wf2) {
    const int idx = blockIdx.x * 256 + threadIdx.x;
    if (idx < 4096) {
        const int ks = idx >> 10, ln = (idx >> 5) & 31, i = idx & 31;
        const int r = ks * 8 + (ln & 3) + ((i & 1) << 2);
        const int f = ((i >> 1) << 3) + (ln >> 2);
        const float v = (r < NRBF) ? Wf1[r * NF + f] : 0.0f;
        const int off = (ks * 32 + ln) * 32 + ((((i >> 2) ^ (ln & 7)) << 2) + (i & 3));
        g_w1p[off] = __uint_as_float(to_tf32(v));
    } else if (idx < 4096 + 16384) {
        const int j = idx - 4096;
        const int ks = j >> 10, ln = (j >> 5) & 31, i = j & 31;
        const int g = ks * 8 + (ln & 3) + ((i & 1) << 2);
        const int f = ((i >> 1) << 3) + (ln >> 2);
        const int off = (ks * 32 + ln) * 32 + ((((i >> 2) ^ (ln & 7)) << 2) + (i & 3));
        g_w2p[off] = __uint_as_float(to_tf32(Wf2[g * NF + f]));
    }
}

// ---------------------------------------------------------------------------
__global__ void in2f_kernel(const float* __restrict__ x,
                            const float* __restrict__ Win) {
    const int row = blockIdx.x;
    __shared__ float xs[NF];
    const int f = threadIdx.x;
    xs[f] = x[row * NF + f];
    __syncthreads();
    float acc = 0.0f;
#pragma unroll 8
    for (int i = 0; i < NF; ++i) acc += xs[i] * Win[i * NF + f];
    g_y[row * NF + f] = acc;
}

// ---------------------------------------------------------------------------
// SMEM layout (bytes)
// ---------------------------------------------------------------------------
#define OFF_H     0          // 64*132*4 = 33792
#define OFF_W2P   33792      // 65536
#define OFF_RBF   99328      // 64*36*4 = 9216 (aliased by PART/Y/RED post-loop)
#define OFF_BF1   108544     // 512
#define OFF_BF2   109056     // 512
#define OFF_MASK  109568     // 256
#define OFF_NJ    109824     // 256
#define OFF_NK    110080     // 256
#define SMEM_BYTES 110336    // 107.75 KB -> 2 blocks/SM

#define NTHREADS 256

__global__ __launch_bounds__(NTHREADS, 2)
void cfconv_mma(const float* __restrict__ r_ij,
                const float* __restrict__ pmask,
                const float* __restrict__ bf1, const float* __restrict__ bf2,
                const float* __restrict__ Wout, const float* __restrict__ bout,
                const int* __restrict__ nj, const int* __restrict__ nk,
                float* __restrict__ out) {
    extern __shared__ __align__(16) char smem[];
    uint32_t* sH   = (uint32_t*)(smem + OFF_H);
    float* sW2p  = (float*)(smem + OFF_W2P);
    uint32_t* sRbf = (uint32_t*)(smem + OFF_RBF);
    float* sBf1  = (float*)(smem + OFF_BF1);
    float* sBf2  = (float*)(smem + OFF_BF2);
    float* sMask = (float*)(smem + OFF_MASK);
    int*   sNj   = (int*)(smem + OFF_NJ);
    int*   sNk   = (int*)(smem + OFF_NK);
    // post-loop aliases into the rbf region
    float* sPart = (float*)(smem + OFF_RBF);           // 2*128 floats
    float* sY    = (float*)(smem + OFF_RBF + 1024);    // 128 floats
    float* sRed  = (float*)(smem + OFF_RBF + 1536);    // 2*128 floats

    const int tid  = threadIdx.x;
    const int wid  = tid >> 5;
    const int lane = tid & 31;
    const int gid  = lane >> 2;
    const int l4   = lane & 3;
    const int wm   = wid >> 2;          // 0..1
    const int wn   = wid & 3;           // 0..3
    const int mbase = wm * 32;
    const int nb4   = wn * 2;
    const int a = blockIdx.x, b = blockIdx.y;
    const int ba = b * AA + a;
    const float* Yb = g_y + b * AA * NF;

    // ---- prologue: copy permuted W2 into smem; biases; zero rbf pad ----
    {
        const uint4* src = (const uint4*)g_w2p;
        uint4* dst = (uint4*)sW2p;
        for (int i = tid; i < 4096; i += NTHREADS) dst[i] = src[i];
    }
    for (int i = tid; i < TILT * RS; i += NTHREADS) sRbf[i] = 0u;
    if (tid < NF) { sBf1[tid] = bf1[tid]; sBf2[tid] = bf2[tid]; }
    __syncthreads();

    float acc[4][2];
#pragma unroll
    for (int j = 0; j < 4; ++j) { acc[j][0] = 0.0f; acc[j][1] = 0.0f; }

    for (int tile = 0; tile < NTIL; ++tile) {
        const int tbase = tile * TILT;

        // ---- stage tile inputs ----
        const float* rsrc = r_ij + ((long)ba * TT + tbase) * NRBF;
        for (int i = tid; i < TILT * NRBF; i += NTHREADS) {
            const int t = i / NRBF, r = i - t * NRBF;
            sRbf[t * RS + r] = to_tf32(rsrc[i]);
        }
        if (tid < TILT) {
            const long p = (long)ba * TT + tbase + tid;
            sMask[tid] = pmask[p];
            sNj[tid] = nj[p];
            sNk[tid] = nk[p];
        }
        __syncthreads();

        float C[2][4][4];
#pragma unroll
        for (int mt = 0; mt < 2; ++mt)
#pragma unroll
            for (int j = 0; j < 4; ++j)
#pragma unroll
                for (int q = 0; q < 4; ++q) C[mt][j][q] = 0.0f;

        // ---- GEMM1: H = rbf @ Wf1 (K=32 padded; B-frags straight from L2) ----
#pragma unroll
        for (int ks = 0; ks < 4; ++ks) {
            uint32_t A[2][4];
#pragma unroll
            for (int mt = 0; mt < 2; ++mt) {
                const int r0 = mbase + mt * 16 + gid;
                const int c0 = ks * 8 + l4;
                A[mt][0] = sRbf[r0 * RS + c0];
                A[mt][1] = sRbf[(r0 + 8) * RS + c0];
                A[mt][2] = sRbf[r0 * RS + c0 + 4];
                A[mt][3] = sRbf[(r0 + 8) * RS + c0 + 4];
            }
            const float4* rowp = (const float4*)(g_w1p) + (ks * 32 + lane) * 8;
            float4 bq[2];
            bq[0] = __ldg(rowp + (nb4 ^ (lane & 7)));
            bq[1] = __ldg(rowp + ((nb4 + 1) ^ (lane & 7)));
            const uint32_t* bu = (const uint32_t*)bq;
#pragma unroll
            for (int mt = 0; mt < 2; ++mt)
#pragma unroll
                for (int j = 0; j < 4; ++j)
                    mma8(C[mt][j], A[mt], bu[2 * j], bu[2 * j + 1]);
        }

        // ---- ssp(C + bf1) -> sH ----
#pragma unroll
        for (int mt = 0; mt < 2; ++mt)
#pragma unroll
            for (int j = 0; j < 4; ++j) {
                const int f0 = wn * 32 + j * 8 + l4 * 2;
                const float2 b1v = *(const float2*)(sBf1 + f0);
                const int r0 = mbase + mt * 16 + gid;
                *(uint2*)(sH + r0 * HS + f0) =
                    make_uint2(to_tf32(ssp(C[mt][j][0] + b1v.x)),
                               to_tf32(ssp(C[mt][j][1] + b1v.y)));
                *(uint2*)(sH + (r0 + 8) * HS + f0) =
                    make_uint2(to_tf32(ssp(C[mt][j][2] + b1v.x)),
                               to_tf32(ssp(C[mt][j][3] + b1v.y)));
            }
        __syncthreads();

        // ---- GEMM2: W = H @ Wf2 (K=128, 16 k-steps, B from smem) ----
#pragma unroll
        for (int mt = 0; mt < 2; ++mt)
#pragma unroll
            for (int j = 0; j < 4; ++j)
#pragma unroll
                for (int q = 0; q < 4; ++q) C[mt][j][q] = 0.0f;
#pragma unroll
        for (int ks = 0; ks < 16; ++ks) {
            uint32_t A[2][4];
#pragma unroll
            for (int mt = 0; mt < 2; ++mt) {
                const int r0 = mbase + mt * 16 + gid;
                const int c0 = ks * 8 + l4;
                A[mt][0] = sH[r0 * HS + c0];
                A[mt][1] = sH[(r0 + 8) * HS + c0];
                A[mt][2] = sH[r0 * HS + c0 + 4];
                A[mt][3] = sH[(r0 + 8) * HS + c0 + 4];
            }
            const float4* rowp = (const float4*)(sW2p + (ks * 32 + lane) * 32);
            float4 bq[2];
            bq[0] = rowp[nb4 ^ (lane & 7)];
            bq[1] = rowp[(nb4 + 1) ^ (lane & 7)];
            const uint32_t* bu = (const uint32_t*)bq;
#pragma unroll
            for (int mt = 0; mt < 2; ++mt)
#pragma unroll
                for (int j = 0; j < 4; ++j)
                    mma8(C[mt][j], A[mt], bu[2 * j], bu[2 * j + 1]);
        }

        // ---- epilogue: acc += (W + bf2) * yj * yk * mask ----
#pragma unroll
        for (int mt = 0; mt < 2; ++mt)
#pragma unroll
            for (int rr = 0; rr < 2; ++rr) {
                const int t = mbase + mt * 16 + gid + rr * 8;
                const float mk = sMask[t];
                const float* yjp = Yb + sNj[t] * NF;
                const float* ykp = Yb + sNk[t] * NF;
#pragma unroll
                for (int j = 0; j < 4; ++j) {
                    const int f0 = wn * 32 + j * 8 + l4 * 2;
                    const float2 b2 = *(const float2*)(sBf2 + f0);
                    const float2 j2 = *(const float2*)(yjp + f0);
                    const float2 k2 = *(const float2*)(ykp + f0);
                    acc[j][0] = fmaf((C[mt][j][rr * 2 + 0] + b2.x),
                                     mk * j2.x * k2.x, acc[j][0]);
                    acc[j][1] = fmaf((C[mt][j][rr * 2 + 1] + b2.y),
                                     mk * j2.y * k2.y, acc[j][1]);
                }
            }
        __syncthreads();
    }

    // ---- reduce over gid within warp ----
#pragma unroll
    for (int s = 4; s < 32; s <<= 1) {
#pragma unroll
        for (int j = 0; j < 4; ++j) {
            acc[j][0] += __shfl_xor_sync(0xffffffffu, acc[j][0], s);
            acc[j][1] += __shfl_xor_sync(0xffffffffu, acc[j][1], s);
        }
    }
    if (lane < 4) {
#pragma unroll
        for (int j = 0; j < 4; ++j) {
            sPart[wm * NF + wn * 32 + j * 8 + lane * 2]     = acc[j][0];
            sPart[wm * NF + wn * 32 + j * 8 + lane * 2 + 1] = acc[j][1];
        }
    }
    __syncthreads();
    if (tid < NF) sY[tid] = sPart[tid] + sPart[NF + tid];
    __syncthreads();

    // ---- f2out: out = ssp(y @ Wout + bout), 2-way K split ----
    {
        const int o = tid & 127;
        const int q = tid >> 7;
        float s = 0.0f;
        const float* Wp = Wout + q * 64 * NF + o;
#pragma unroll 8
        for (int f = 0; f < 64; ++f) s += sY[q * 64 + f] * Wp[f * NF];
        sRed[q * NF + o] = s;
    }
    __syncthreads();
    if (tid < NF)
        out[(long)ba * NF + tid] = ssp(sRed[tid] + sRed[NF + tid] + bout[tid]);
}

// ---------------------------------------------------------------------------
extern "C" void kernel_launch(void* const* d_in, const int* in_sizes, int n_in,
                              void* d_out, int out_size) {
    const float* x    = (const float*)d_in[0];
    const float* r_ij = (const float*)d_in[1];
    const float* mask = (const float*)d_in[2];
    const float* Wf1  = (const float*)d_in[3];
    const float* bf1  = (const float*)d_in[4];
    const float* Wf2  = (const float*)d_in[5];
    const float* bf2  = (const float*)d_in[6];
    const float* Win  = (const float*)d_in[7];
    const float* Wout = (const float*)d_in[8];
    const float* bout = (const float*)d_in[9];
    const int*   nj   = (const int*)d_in[10];
    const int*   nk   = (const int*)d_in[11];
    float* out = (float*)d_out;

    prep_kernel<<<80, 256>>>(Wf1, Wf2);
    in2f_kernel<<<BB * AA, NF>>>(x, Win);

    cudaFuncSetAttribute(cfconv_mma,
                         cudaFuncAttributeMaxDynamicSharedMemorySize, SMEM_BYTES);
    dim3 grid(AA, BB);
    cfconv_mma<<<grid, NTHREADS, SMEM_BYTES>>>(r_ij, mask, bf1, bf2,
                                               Wout, bout, nj, nk, out);
}

// round 6
// speedup vs baseline: 2.7996x; 1.1126x over previous
#include <cuda_runtime.h>
#include <cstdint>

#define BB   2
#define AA   512
#define TT   512
#define NF   128
#define NRBF 25
#define TILT 64
#define NTIL (TT / TILT)   // 8
#define TRBF (TILT * NRBF) // 1600

#define RS 36     // sRbf row stride (floats)
#define HS 132    // sH   row stride (floats)

__device__ float g_y[BB * AA * NF];
__device__ float g_w1p[4 * 32 * 32];
__device__ float g_w2p[16 * 32 * 32];

// shifted softplus, 1 MUFU + polynomial log1p.
// ln(1+u), u in [0,1]: degree-6 poly in x=2u-1 (Chebyshev-derived, |err|<7e-6).
// constant term has ln2 pre-subtracted.
__device__ __forceinline__ float ssp(float v) {
    const float m = fmaxf(v, 0.0f);
    const float u = __expf(-fabsf(v));          // 1 MUFU + 1 mul
    const float x = fmaf(2.0f, u, -1.0f);
    float p = -0.00027211f;
    p = fmaf(p, x, 0.00095152f);
    p = fmaf(p, x, -0.00305808f);
    p = fmaf(p, x, 0.01227896f);
    p = fmaf(p, x, -0.05556132f);
    p = fmaf(p, x, 0.33334183f);
    p = fmaf(p, x, -0.28768771f);               // 0.40545947 - ln2
    return m + p;
}
__device__ __forceinline__ uint32_t to_tf32(float v) {
    uint32_t r;
    asm("cvt.rna.tf32.f32 %0, %1;" : "=r"(r) : "f"(v));
    return r;
}
__device__ __forceinline__ void mma8(float* c, const uint32_t* a,
                                     uint32_t b0, uint32_t b1) {
    asm volatile(
        "mma.sync.aligned.m16n8k8.row.col.f32.tf32.tf32.f32 "
        "{%0,%1,%2,%3}, {%4,%5,%6,%7}, {%8,%9}, {%0,%1,%2,%3};"
        : "+f"(c[0]), "+f"(c[1]), "+f"(c[2]), "+f"(c[3])
        : "r"(a[0]), "r"(a[1]), "r"(a[2]), "r"(a[3]), "r"(b0), "r"(b1));
}

// ---------------------------------------------------------------------------
__global__ void prep_kernel(const float* __restrict__ Wf1,
                            const float* __restrict__ Wf2) {
    const int idx = blockIdx.x * 256 + threadIdx.x;
    if (idx < 4096) {
        const int ks = idx >> 10, ln = (idx >> 5) & 31, i = idx & 31;
        const int r = ks * 8 + (ln & 3) + ((i & 1) << 2);
        const int f = ((i >> 1) << 3) + (ln >> 2);
        const float v = (r < NRBF) ? Wf1[r * NF + f] : 0.0f;
        const int off = (ks * 32 + ln) * 32 + ((((i >> 2) ^ (ln & 7)) << 2) + (i & 3));
        g_w1p[off] = __uint_as_float(to_tf32(v));
    } else if (idx < 4096 + 16384) {
        const int j = idx - 4096;
        const int ks = j >> 10, ln = (j >> 5) & 31, i = j & 31;
        const int g = ks * 8 + (ln & 3) + ((i & 1) << 2);
        const int f = ((i >> 1) << 3) + (ln >> 2);
        const int off = (ks * 32 + ln) * 32 + ((((i >> 2) ^ (ln & 7)) << 2) + (i & 3));
        g_w2p[off] = __uint_as_float(to_tf32(Wf2[g * NF + f]));
    }
}

// ---------------------------------------------------------------------------
__global__ void in2f_kernel(const float* __restrict__ x,
                            const float* __restrict__ Win) {
    const int row = blockIdx.x;
    __shared__ float xs[NF];
    const int f = threadIdx.x;
    xs[f] = x[row * NF + f];
    __syncthreads();
    float acc = 0.0f;
#pragma unroll 8
    for (int i = 0; i < NF; ++i) acc += xs[i] * Win[i * NF + f];
    g_y[row * NF + f] = acc;
}

// ---------------------------------------------------------------------------
// SMEM layout (bytes)
// ---------------------------------------------------------------------------
#define OFF_H     0          // 64*132*4 = 33792
#define OFF_W2P   33792      // 65536
#define OFF_RBF   99328      // 9216 (aliased by PART/Y/RED post-loop)
#define OFF_BF1   108544     // 512
#define OFF_BF2   109056     // 512
#define OFF_MASK  109568     // 2*64*4 = 512
#define OFF_NJ    110080     // 512
#define OFF_NK    110592     // 512
#define SMEM_BYTES 111104    // 108.5 KB -> 2 blocks/SM

#define NTHREADS 256

__global__ __launch_bounds__(NTHREADS, 2)
void cfconv_mma(const float* __restrict__ r_ij,
                const float* __restrict__ pmask,
                const float* __restrict__ bf1, const float* __restrict__ bf2,
                const float* __restrict__ Wout, const float* __restrict__ bout,
                const int* __restrict__ nj, const int* __restrict__ nk,
                float* __restrict__ out) {
    extern __shared__ __align__(16) char smem[];
    uint32_t* sH   = (uint32_t*)(smem + OFF_H);
    float* sW2p  = (float*)(smem + OFF_W2P);
    uint32_t* sRbf = (uint32_t*)(smem + OFF_RBF);
    float* sBf1  = (float*)(smem + OFF_BF1);
    float* sBf2  = (float*)(smem + OFF_BF2);
    float* sMask = (float*)(smem + OFF_MASK);   // [2][64]
    int*   sNj   = (int*)(smem + OFF_NJ);       // [2][64]
    int*   sNk   = (int*)(smem + OFF_NK);       // [2][64]
    float* sPart = (float*)(smem + OFF_RBF);
    float* sY    = (float*)(smem + OFF_RBF + 1024);
    float* sRed  = (float*)(smem + OFF_RBF + 1536);

    const int tid  = threadIdx.x;
    const int wid  = tid >> 5;
    const int lane = tid & 31;
    const int gid  = lane >> 2;
    const int l4   = lane & 3;
    const int wm   = wid >> 2;
    const int wn   = wid & 3;
    const int mbase = wm * 32;
    const int nb4   = wn * 2;
    const int a = blockIdx.x, b = blockIdx.y;
    const int ba = b * AA + a;
    const float* Yb = g_y + b * AA * NF;

    // ---- prologue: copy permuted W2; biases; zero rbf pad; stage tile 0 ----
    {
        const uint4* src = (const uint4*)g_w2p;
        uint4* dst = (uint4*)sW2p;
        for (int i = tid; i < 4096; i += NTHREADS) dst[i] = src[i];
    }
    for (int i = tid; i < TILT * RS; i += NTHREADS) sRbf[i] = 0u;
    if (tid < NF) { sBf1[tid] = bf1[tid]; sBf2[tid] = bf2[tid]; }
    __syncthreads();   // rbf zeros visible before tile-0 partial overwrite
    {
        const float* rsrc = r_ij + (long)ba * TT * NRBF;
        for (int i = tid; i < TRBF; i += NTHREADS) {
            const int t = i / NRBF, r = i - t * NRBF;
            sRbf[t * RS + r] = to_tf32(rsrc[i]);
        }
        if (tid < TILT) {
            const long p = (long)ba * TT + tid;
            sMask[tid] = pmask[p];
            sNj[tid] = nj[p];
            sNk[tid] = nk[p];
        }
    }
    __syncthreads();

    float acc[4][2];
#pragma unroll
    for (int j = 0; j < 4; ++j) { acc[j][0] = 0.0f; acc[j][1] = 0.0f; }

    for (int tile = 0; tile < NTIL; ++tile) {
        const int cur = tile & 1;
        const int nxt = cur ^ 1;

        float C[2][4][4];
#pragma unroll
        for (int mt = 0; mt < 2; ++mt)
#pragma unroll
            for (int j = 0; j < 4; ++j)
#pragma unroll
                for (int q = 0; q < 4; ++q) C[mt][j][q] = 0.0f;

        // ---- GEMM1: H = rbf @ Wf1 (K=32 padded; B-frags from L2) ----
#pragma unroll
        for (int ks = 0; ks < 4; ++ks) {
            uint32_t A[2][4];
#pragma unroll
            for (int mt = 0; mt < 2; ++mt) {
                const int r0 = mbase + mt * 16 + gid;
                const int c0 = ks * 8 + l4;
                A[mt][0] = sRbf[r0 * RS + c0];
                A[mt][1] = sRbf[(r0 + 8) * RS + c0];
                A[mt][2] = sRbf[r0 * RS + c0 + 4];
                A[mt][3] = sRbf[(r0 + 8) * RS + c0 + 4];
            }
            const float4* rowp = (const float4*)(g_w1p) + (ks * 32 + lane) * 8;
            float4 bq[2];
            bq[0] = __ldg(rowp + (nb4 ^ (lane & 7)));
            bq[1] = __ldg(rowp + ((nb4 + 1) ^ (lane & 7)));
            const uint32_t* bu = (const uint32_t*)bq;
#pragma unroll
            for (int mt = 0; mt < 2; ++mt)
#pragma unroll
                for (int j = 0; j < 4; ++j)
                    mma8(C[mt][j], A[mt], bu[2 * j], bu[2 * j + 1]);
        }

        // ---- ssp(C + bf1) -> sH ----
#pragma unroll
        for (int mt = 0; mt < 2; ++mt)
#pragma unroll
            for (int j = 0; j < 4; ++j) {
                const int f0 = wn * 32 + j * 8 + l4 * 2;
                const float2 b1v = *(const float2*)(sBf1 + f0);
                const int r0 = mbase + mt * 16 + gid;
                *(uint2*)(sH + r0 * HS + f0) =
                    make_uint2(to_tf32(ssp(C[mt][j][0] + b1v.x)),
                               to_tf32(ssp(C[mt][j][1] + b1v.y)));
                *(uint2*)(sH + (r0 + 8) * HS + f0) =
                    make_uint2(to_tf32(ssp(C[mt][j][2] + b1v.x)),
                               to_tf32(ssp(C[mt][j][3] + b1v.y)));
            }

        // ---- prefetch next tile into registers (LDG overlaps GEMM2) ----
        float rstg[7];
        float stg_mk = 0.0f; int stg_j = 0, stg_k = 0;
        if (tile < NTIL - 1) {
            const float* rnext = r_ij + ((long)ba * TT + (tile + 1) * TILT) * NRBF;
#pragma unroll
            for (int q = 0; q < 7; ++q) {
                const int i = tid + q * NTHREADS;
                if (i < TRBF) rstg[q] = rnext[i];
            }
            if (tid < TILT) {
                const long p = (long)ba * TT + (tile + 1) * TILT + tid;
                stg_mk = pmask[p];
                stg_j = nj[p];
                stg_k = nk[p];
            }
        }
        __syncthreads();   // sync1: sH visible, staged arrays free

        // ---- GEMM2: W = H @ Wf2 (K=128, 16 k-steps, B from smem) ----
#pragma unroll
        for (int mt = 0; mt < 2; ++mt)
#pragma unroll
            for (int j = 0; j < 4; ++j)
#pragma unroll
                for (int q = 0; q < 4; ++q) C[mt][j][q] = 0.0f;
#pragma unroll
        for (int ks = 0; ks < 16; ++ks) {
            uint32_t A[2][4];
#pragma unroll
            for (int mt = 0; mt < 2; ++mt) {
                const int r0 = mbase + mt * 16 + gid;
                const int c0 = ks * 8 + l4;
                A[mt][0] = sH[r0 * HS + c0];
                A[mt][1] = sH[(r0 + 8) * HS + c0];
                A[mt][2] = sH[r0 * HS + c0 + 4];
                A[mt][3] = sH[(r0 + 8) * HS + c0 + 4];
            }
            const float4* rowp = (const float4*)(sW2p + (ks * 32 + lane) * 32);
            float4 bq[2];
            bq[0] = rowp[nb4 ^ (lane & 7)];
            bq[1] = rowp[(nb4 + 1) ^ (lane & 7)];
            const uint32_t* bu = (const uint32_t*)bq;
#pragma unroll
            for (int mt = 0; mt < 2; ++mt)
#pragma unroll
                for (int j = 0; j < 4; ++j)
                    mma8(C[mt][j], A[mt], bu[2 * j], bu[2 * j + 1]);
        }

        // ---- epilogue: acc += (W + bf2) * yj * yk * mask ----
#pragma unroll
        for (int mt = 0; mt < 2; ++mt)
#pragma unroll
            for (int rr = 0; rr < 2; ++rr) {
                const int t = mbase + mt * 16 + gid + rr * 8;
                const float mk = sMask[cur * TILT + t];
                const float* yjp = Yb + sNj[cur * TILT + t] * NF;
                const float* ykp = Yb + sNk[cur * TILT + t] * NF;
#pragma unroll
                for (int j = 0; j < 4; ++j) {
                    const int f0 = wn * 32 + j * 8 + l4 * 2;
                    const float2 b2 = *(const float2*)(sBf2 + f0);
                    const float2 j2 = *(const float2*)(yjp + f0);
                    const float2 k2 = *(const float2*)(ykp + f0);
                    acc[j][0] = fmaf((C[mt][j][rr * 2 + 0] + b2.x),
                                     mk * j2.x * k2.x, acc[j][0]);
                    acc[j][1] = fmaf((C[mt][j][rr * 2 + 1] + b2.y),
                                     mk * j2.y * k2.y, acc[j][1]);
                }
            }

        // ---- store staged tile (rbf region free since GEMM1 of this tile) ----
        if (tile < NTIL - 1) {
#pragma unroll
            for (int q = 0; q < 7; ++q) {
                const int i = tid + q * NTHREADS;
                if (i < TRBF) {
                    const int t = i / NRBF, r = i - t * NRBF;
                    sRbf[t * RS + r] = to_tf32(rstg[q]);
                }
            }
            if (tid < TILT) {
                sMask[nxt * TILT + tid] = stg_mk;
                sNj[nxt * TILT + tid] = stg_j;
                sNk[nxt * TILT + tid] = stg_k;
            }
        }
        __syncthreads();   // sync2
    }

    // ---- reduce over gid within warp ----
#pragma unroll
    for (int s = 4; s < 32; s <<= 1) {
#pragma unroll
        for (int j = 0; j < 4; ++j) {
            acc[j][0] += __shfl_xor_sync(0xffffffffu, acc[j][0], s);
            acc[j][1] += __shfl_xor_sync(0xffffffffu, acc[j][1], s);
        }
    }
    if (lane < 4) {
#pragma unroll
        for (int j = 0; j < 4; ++j) {
            sPart[wm * NF + wn * 32 + j * 8 + lane * 2]     = acc[j][0];
            sPart[wm * NF + wn * 32 + j * 8 + lane * 2 + 1] = acc[j][1];
        }
    }
    __syncthreads();
    if (tid < NF) sY[tid] = sPart[tid] + sPart[NF + tid];
    __syncthreads();

    // ---- f2out ----
    {
        const int o = tid & 127;
        const int q = tid >> 7;
        float s = 0.0f;
        const float* Wp = Wout + q * 64 * NF + o;
#pragma unroll 8
        for (int f = 0; f < 64; ++f) s += sY[q * 64 + f] * Wp[f * NF];
        sRed[q * NF + o] = s;
    }
    __syncthreads();
    if (tid < NF)
        out[(long)ba * NF + tid] = ssp(sRed[tid] + sRed[NF + tid] + bout[tid]);
}

// ---------------------------------------------------------------------------
extern "C" void kernel_launch(void* const* d_in, const int* in_sizes, int n_in,
                              void* d_out, int out_size) {
    const float* x    = (const float*)d_in[0];
    const float* r_ij = (const float*)d_in[1];
    const float* mask = (const float*)d_in[2];
    const float* Wf1  = (const float*)d_in[3];
    const float* bf1  = (const float*)d_in[4];
    const float* Wf2  = (const float*)d_in[5];
    const float* bf2  = (const float*)d_in[6];
    const float* Win  = (const float*)d_in[7];
    const float* Wout = (const float*)d_in[8];
    const float* bout = (const float*)d_in[9];
    const int*   nj   = (const int*)d_in[10];
    const int*   nk   = (const int*)d_in[11];
    float* out = (float*)d_out;

    prep_kernel<<<80, 256>>>(Wf1, Wf2);
    in2f_kernel<<<BB * AA, NF>>>(x, Win);

    cudaFuncSetAttribute(cfconv_mma,
                         cudaFuncAttributeMaxDynamicSharedMemorySize, SMEM_BYTES);
    dim3 grid(AA, BB);
    cfconv_mma<<<grid, NTHREADS, SMEM_BYTES>>>(r_ij, mask, bf1, bf2,
                                               Wout, bout, nj, nk, out);
}

// round 7
// speedup vs baseline: 4.0206x; 1.4361x over previous
#include <cuda_runtime.h>
#include <cuda_fp16.h>
#include <cstdint>

#define BB   2
#define AA   512
#define TT   512
#define NF   128
#define NRBF 25
#define TILT 64
#define NTIL (TT / TILT)   // 8
#define TRBF (TILT * NRBF) // 1600

#define RSH 40    // sRbf row stride (halves): 32 + 8 pad
#define HSH 136   // sH   row stride (halves): 128 + 8 pad

__device__ float    g_y[BB * AA * NF];
__device__ uint32_t g_w1ph[2 * 32 * 32];   // fp16x2 Wf1 B-fragments (K padded to 32)
__device__ uint32_t g_w2ph[8 * 32 * 32];   // fp16x2 Wf2 B-fragments

// shifted softplus: 1 MUFU + deg-6 poly log1p (|err|<7e-6), ln2 pre-subtracted
__device__ __forceinline__ float ssp(float v) {
    const float m = fmaxf(v, 0.0f);
    const float u = __expf(-fabsf(v));
    const float x = fmaf(2.0f, u, -1.0f);
    float p = -0.00027211f;
    p = fmaf(p, x, 0.00095152f);
    p = fmaf(p, x, -0.00305808f);
    p = fmaf(p, x, 0.01227896f);
    p = fmaf(p, x, -0.05556132f);
    p = fmaf(p, x, 0.33334183f);
    p = fmaf(p, x, -0.28768771f);
    return m + p;
}
__device__ __forceinline__ uint32_t smem_u32(const void* p) {
    uint32_t a;
    asm("{ .reg .u64 t; cvta.to.shared.u64 t, %1; cvt.u32.u64 %0, t; }"
        : "=r"(a) : "l"(p));
    return a;
}
__device__ __forceinline__ void mma16(float* c, const uint32_t* a,
                                      uint32_t b0, uint32_t b1) {
    asm volatile(
        "mma.sync.aligned.m16n8k16.row.col.f32.f16.f16.f32 "
        "{%0,%1,%2,%3}, {%4,%5,%6,%7}, {%8,%9}, {%0,%1,%2,%3};"
        : "+f"(c[0]), "+f"(c[1]), "+f"(c[2]), "+f"(c[3])
        : "r"(a[0]), "r"(a[1]), "r"(a[2]), "r"(a[3]), "r"(b0), "r"(b1));
}
__device__ __forceinline__ void ldmat4(uint32_t* r, uint32_t addr) {
    asm volatile(
        "ldmatrix.sync.aligned.m8n8.x4.shared.b16 {%0,%1,%2,%3}, [%4];"
        : "=r"(r[0]), "=r"(r[1]), "=r"(r[2]), "=r"(r[3]) : "r"(addr));
}
__device__ __forceinline__ uint32_t packh2(float lo, float hi) {
    __half2 h = __floats2half2_rn(lo, hi);
    return *reinterpret_cast<uint32_t*>(&h);
}

// ---------------------------------------------------------------------------
// fused prep (weight tables) + in2f (y = x @ Win)
// blocks 0..511: in2f (2 rows each); blocks 512..551: prep
// ---------------------------------------------------------------------------
__global__ void prep_in2f_kernel(const float* __restrict__ x,
                                 const float* __restrict__ Win,
                                 const float* __restrict__ Wf1,
                                 const float* __restrict__ Wf2) {
    if (blockIdx.x < 512) {
        __shared__ float xs[2][NF];
        const int sub = threadIdx.x >> 7;
        const int f = threadIdx.x & 127;
        const int row = blockIdx.x * 2 + sub;
        xs[sub][f] = x[row * NF + f];
        __syncthreads();
        float acc = 0.0f;
#pragma unroll 8
        for (int i = 0; i < NF; ++i) acc += xs[sub][i] * Win[i * NF + f];
        g_y[row * NF + f] = acc;
    } else {
        const int idx = (blockIdx.x - 512) * 256 + threadIdx.x;
        if (idx < 2048) {
            const int ks = idx >> 10, rem = idx & 1023;
            const int lane = rem >> 5, i = rem & 31;
            const int j = i >> 1, r = i & 1;
            const int n = j * 8 + (lane >> 2);
            const int k0 = ks * 16 + r * 8 + (lane & 3) * 2;
            const float v0 = (k0 < NRBF) ? Wf1[k0 * NF + n] : 0.0f;
            const float v1 = (k0 + 1 < NRBF) ? Wf1[(k0 + 1) * NF + n] : 0.0f;
            const int off = (ks * 32 + lane) * 32 +
                            ((((i >> 2) ^ (lane & 7)) << 2) + (i & 3));
            g_w1ph[off] = packh2(v0, v1);
        } else if (idx < 2048 + 8192) {
            const int t = idx - 2048;
            const int ks = t >> 10, rem = t & 1023;
            const int lane = rem >> 5, i = rem & 31;
            const int j = i >> 1, r = i & 1;
            const int n = j * 8 + (lane >> 2);
            const int k0 = ks * 16 + r * 8 + (lane & 3) * 2;
            const int off = (ks * 32 + lane) * 32 +
                            ((((i >> 2) ^ (lane & 7)) << 2) + (i & 3));
            g_w2ph[off] = packh2(Wf2[k0 * NF + n], Wf2[(k0 + 1) * NF + n]);
        }
    }
}

// ---------------------------------------------------------------------------
// SMEM layout (bytes)
// ---------------------------------------------------------------------------
#define OFF_H     0          // 64*136*2 = 17408 (fp16 H)
#define OFF_W2P   17408      // 32768 (aliased by PART/Y/RED post-loop)
#define OFF_RBF   50176      // 64*40*2 = 5120 (fp16 rbf, K padded)
#define OFF_BF1   55296      // 512
#define OFF_BF2   55808      // 512
#define OFF_MASK  56320      // 2*64*4
#define OFF_NJ    56832
#define OFF_NK    57344
#define SMEM_BYTES 57856     // 56.5KB -> 2 blocks/SM easily

#define NTHREADS 256

__global__ __launch_bounds__(NTHREADS, 2)
void cfconv_mma(const float* __restrict__ r_ij,
                const float* __restrict__ pmask,
                const float* __restrict__ bf1, const float* __restrict__ bf2,
                const float* __restrict__ Wout, const float* __restrict__ bout,
                const int* __restrict__ nj, const int* __restrict__ nk,
                float* __restrict__ out) {
    extern __shared__ __align__(16) char smem[];
    __half*   sHh   = (__half*)(smem + OFF_H);
    uint32_t* sW2p  = (uint32_t*)(smem + OFF_W2P);
    __half*   sRbfH = (__half*)(smem + OFF_RBF);
    float* sBf1  = (float*)(smem + OFF_BF1);
    float* sBf2  = (float*)(smem + OFF_BF2);
    float* sMask = (float*)(smem + OFF_MASK);
    int*   sNj   = (int*)(smem + OFF_NJ);
    int*   sNk   = (int*)(smem + OFF_NK);
    float* sPart = (float*)(smem + OFF_W2P);
    float* sY    = (float*)(smem + OFF_W2P + 1024);
    float* sRed  = (float*)(smem + OFF_W2P + 1536);

    const int tid  = threadIdx.x;
    const int wid  = tid >> 5;
    const int lane = tid & 31;
    const int gid  = lane >> 2;
    const int l4   = lane & 3;
    const int wm   = wid >> 2;          // 0..1
    const int wn   = wid & 3;           // 0..3
    const int mbase = wm * 32;
    const int nb4   = wn * 2;
    const int a = blockIdx.x, b = blockIdx.y;
    const int ba = b * AA + a;
    const float* Yb = g_y + b * AA * NF;

    // ldmatrix lane addressing
    const int lrow  = (lane & 7) + ((lane >> 3) & 1) * 8;
    const int lkh   = ((lane >> 4) & 1) * 8;
    uint32_t addrR[2], addrH[2];
#pragma unroll
    for (int mt = 0; mt < 2; ++mt) {
        addrR[mt] = smem_u32(sRbfH + (mbase + mt * 16 + lrow) * RSH + lkh);
        addrH[mt] = smem_u32(sHh + (mbase + mt * 16 + lrow) * HSH + lkh);
    }

    // ---- prologue ----
    {
        const uint4* src = (const uint4*)g_w2ph;
        uint4* dst = (uint4*)sW2p;
        for (int i = tid; i < 2048; i += NTHREADS) dst[i] = src[i];
    }
    {   // zero fp16 rbf (covers K padding)
        uint32_t* z = (uint32_t*)sRbfH;
        for (int i = tid; i < (TILT * RSH) / 2; i += NTHREADS) z[i] = 0u;
    }
    if (tid < NF) { sBf1[tid] = bf1[tid]; sBf2[tid] = bf2[tid]; }

    // hoist GEMM1 B-fragments (tile-invariant): 16 regs
    uint32_t w1b[2][8];
#pragma unroll
    for (int ks = 0; ks < 2; ++ks) {
        const uint4* rowp = (const uint4*)g_w1ph + (ks * 32 + lane) * 8;
        uint4 q0 = __ldg(rowp + (nb4 ^ (lane & 7)));
        uint4 q1 = __ldg(rowp + ((nb4 + 1) ^ (lane & 7)));
        w1b[ks][0] = q0.x; w1b[ks][1] = q0.y; w1b[ks][2] = q0.z; w1b[ks][3] = q0.w;
        w1b[ks][4] = q1.x; w1b[ks][5] = q1.y; w1b[ks][6] = q1.z; w1b[ks][7] = q1.w;
    }
    __syncthreads();     // rbf zeros visible
    {   // stage tile 0
        const float* rsrc = r_ij + (long)ba * TT * NRBF;
        for (int i = tid; i < TRBF; i += NTHREADS) {
            const int t = i / NRBF, r = i - t * NRBF;
            sRbfH[t * RSH + r] = __float2half_rn(rsrc[i]);
        }
        if (tid < TILT) {
            const long p = (long)ba * TT + tid;
            sMask[tid] = pmask[p];
            sNj[tid] = nj[p];
            sNk[tid] = nk[p];
        }
    }
    __syncthreads();

    float acc[4][2];
#pragma unroll
    for (int j = 0; j < 4; ++j) { acc[j][0] = 0.0f; acc[j][1] = 0.0f; }

    for (int tile = 0; tile < NTIL; ++tile) {
        const int cur = tile & 1;
        const int nxt = cur ^ 1;

        float C[2][4][4];
#pragma unroll
        for (int mt = 0; mt < 2; ++mt)
#pragma unroll
            for (int j = 0; j < 4; ++j)
#pragma unroll
                for (int q = 0; q < 4; ++q) C[mt][j][q] = 0.0f;

        // ---- GEMM1: H = rbf @ Wf1 (fp16, K=32, 2 k16-steps) ----
#pragma unroll
        for (int ks = 0; ks < 2; ++ks) {
            uint32_t A[2][4];
            ldmat4(A[0], addrR[0] + ks * 32);
            ldmat4(A[1], addrR[1] + ks * 32);
#pragma unroll
            for (int mt = 0; mt < 2; ++mt)
#pragma unroll
                for (int j = 0; j < 4; ++j)
                    mma16(C[mt][j], A[mt], w1b[ks][2 * j], w1b[ks][2 * j + 1]);
        }

        // ---- ssp(C + bf1) -> sH (fp16) ----
#pragma unroll
        for (int mt = 0; mt < 2; ++mt)
#pragma unroll
            for (int j = 0; j < 4; ++j) {
                const int f0 = wn * 32 + j * 8 + l4 * 2;
                const float2 b1v = *(const float2*)(sBf1 + f0);
                const int r0 = mbase + mt * 16 + gid;
                *(__half2*)(sHh + r0 * HSH + f0) =
                    __floats2half2_rn(ssp(C[mt][j][0] + b1v.x),
                                      ssp(C[mt][j][1] + b1v.y));
                *(__half2*)(sHh + (r0 + 8) * HSH + f0) =
                    __floats2half2_rn(ssp(C[mt][j][2] + b1v.x),
                                      ssp(C[mt][j][3] + b1v.y));
            }

        // ---- prefetch next tile into registers ----
        float rstg[7];
        float stg_mk = 0.0f; int stg_j = 0, stg_k = 0;
        if (tile < NTIL - 1) {
            const float* rnext = r_ij + ((long)ba * TT + (tile + 1) * TILT) * NRBF;
#pragma unroll
            for (int q = 0; q < 7; ++q) {
                const int i = tid + q * NTHREADS;
                if (i < TRBF) rstg[q] = rnext[i];
            }
            if (tid < TILT) {
                const long p = (long)ba * TT + (tile + 1) * TILT + tid;
                stg_mk = pmask[p];
                stg_j = nj[p];
                stg_k = nk[p];
            }
        }
        __syncthreads();   // sync1: sH visible

        // ---- GEMM2: W = H @ Wf2 (fp16, K=128, 8 k16-steps) ----
#pragma unroll
        for (int mt = 0; mt < 2; ++mt)
#pragma unroll
            for (int j = 0; j < 4; ++j)
#pragma unroll
                for (int q = 0; q < 4; ++q) C[mt][j][q] = 0.0f;
#pragma unroll
        for (int ks = 0; ks < 8; ++ks) {
            uint32_t A[2][4];
            ldmat4(A[0], addrH[0] + ks * 32);
            ldmat4(A[1], addrH[1] + ks * 32);
            const uint4* rowp = (const uint4*)sW2p + (ks * 32 + lane) * 8;
            uint4 q0 = rowp[nb4 ^ (lane & 7)];
            uint4 q1 = rowp[(nb4 + 1) ^ (lane & 7)];
            uint32_t bu[8] = {q0.x, q0.y, q0.z, q0.w, q1.x, q1.y, q1.z, q1.w};
#pragma unroll
            for (int mt = 0; mt < 2; ++mt)
#pragma unroll
                for (int j = 0; j < 4; ++j)
                    mma16(C[mt][j], A[mt], bu[2 * j], bu[2 * j + 1]);
        }

        // ---- epilogue: acc += (W + bf2) * yj * yk * mask ----
#pragma unroll
        for (int mt = 0; mt < 2; ++mt)
#pragma unroll
            for (int rr = 0; rr < 2; ++rr) {
                const int t = mbase + mt * 16 + gid + rr * 8;
                const float mk = sMask[cur * TILT + t];
                const float* yjp = Yb + sNj[cur * TILT + t] * NF;
                const float* ykp = Yb + sNk[cur * TILT + t] * NF;
#pragma unroll
                for (int j = 0; j < 4; ++j) {
                    const int f0 = wn * 32 + j * 8 + l4 * 2;
                    const float2 b2 = *(const float2*)(sBf2 + f0);
                    const float2 j2 = *(const float2*)(yjp + f0);
                    const float2 k2 = *(const float2*)(ykp + f0);
                    acc[j][0] = fmaf((C[mt][j][rr * 2 + 0] + b2.x),
                                     mk * j2.x * k2.x, acc[j][0]);
                    acc[j][1] = fmaf((C[mt][j][rr * 2 + 1] + b2.y),
                                     mk * j2.y * k2.y, acc[j][1]);
                }
            }

        // ---- store staged tile ----
        if (tile < NTIL - 1) {
#pragma unroll
            for (int q = 0; q < 7; ++q) {
                const int i = tid + q * NTHREADS;
                if (i < TRBF) {
                    const int t = i / NRBF, r = i - t * NRBF;
                    sRbfH[t * RSH + r] = __float2half_rn(rstg[q]);
                }
            }
            if (tid < TILT) {
                sMask[nxt * TILT + tid] = stg_mk;
                sNj[nxt * TILT + tid] = stg_j;
                sNk[nxt * TILT + tid] = stg_k;
            }
        }
        __syncthreads();   // sync2
    }

    // ---- reduce over gid within warp ----
#pragma unroll
    for (int s = 4; s < 32; s <<= 1) {
#pragma unroll
        for (int j = 0; j < 4; ++j) {
            acc[j][0] += __shfl_xor_sync(0xffffffffu, acc[j][0], s);
            acc[j][1] += __shfl_xor_sync(0xffffffffu, acc[j][1], s);
        }
    }
    if (lane < 4) {
#pragma unroll
        for (int j = 0; j < 4; ++j) {
            sPart[wm * NF + wn * 32 + j * 8 + lane * 2]     = acc[j][0];
            sPart[wm * NF + wn * 32 + j * 8 + lane * 2 + 1] = acc[j][1];
        }
    }
    __syncthreads();
    if (tid < NF) sY[tid] = sPart[tid] + sPart[NF + tid];
    __syncthreads();

    // ---- f2out ----
    {
        const int o = tid & 127;
        const int q = tid >> 7;
        float s = 0.0f;
        const float* Wp = Wout + q * 64 * NF + o;
#pragma unroll 8
        for (int f = 0; f < 64; ++f) s += sY[q * 64 + f] * Wp[f * NF];
        sRed[q * NF + o] = s;
    }
    __syncthreads();
    if (tid < NF)
        out[(long)ba * NF + tid] = ssp(sRed[tid] + sRed[NF + tid] + bout[tid]);
}

// ---------------------------------------------------------------------------
extern "C" void kernel_launch(void* const* d_in, const int* in_sizes, int n_in,
                              void* d_out, int out_size) {
    const float* x    = (const float*)d_in[0];
    const float* r_ij = (const float*)d_in[1];
    const float* mask = (const float*)d_in[2];
    const float* Wf1  = (const float*)d_in[3];
    const float* bf1  = (const float*)d_in[4];
    const float* Wf2  = (const float*)d_in[5];
    const float* bf2  = (const float*)d_in[6];
    const float* Win  = (const float*)d_in[7];
    const float* Wout = (const float*)d_in[8];
    const float* bout = (const float*)d_in[9];
    const int*   nj   = (const int*)d_in[10];
    const int*   nk   = (const int*)d_in[11];
    float* out = (float*)d_out;

    prep_in2f_kernel<<<552, 256>>>(x, Win, Wf1, Wf2);

    cudaFuncSetAttribute(cfconv_mma,
                         cudaFuncAttributeMaxDynamicSharedMemorySize, SMEM_BYTES);
    dim3 grid(AA, BB);
    cfconv_mma<<<grid, NTHREADS, SMEM_BYTES>>>(r_ij, mask, bf1, bf2,
                                               Wout, bout, nj, nk, out);
}

// round 8
// speedup vs baseline: 4.7612x; 1.1842x over previous
#include <cuda_runtime.h>
#include <cuda_fp16.h>
#include <cstdint>

#define BB   2
#define AA   512
#define TT   512
#define NF   128
#define NRBF 25
#define TILT 64
#define NTIL (TT / TILT)   // 8
#define TRBF (TILT * NRBF) // 1600

#define RSH 40    // sRbf row stride (halves)
#define HSH 136   // sH   row stride (halves)
#define WS  136   // sW   row stride (floats)

__device__ float    g_y[BB * AA * NF];
__device__ uint32_t g_w1ph[2 * 32 * 32];
__device__ uint32_t g_w2ph[8 * 32 * 32];

// shifted softplus: 1 MUFU + deg-6 poly log1p (|err|<7e-6), ln2 pre-subtracted
__device__ __forceinline__ float ssp(float v) {
    const float m = fmaxf(v, 0.0f);
    const float u = __expf(-fabsf(v));
    const float x = fmaf(2.0f, u, -1.0f);
    float p = -0.00027211f;
    p = fmaf(p, x, 0.00095152f);
    p = fmaf(p, x, -0.00305808f);
    p = fmaf(p, x, 0.01227896f);
    p = fmaf(p, x, -0.05556132f);
    p = fmaf(p, x, 0.33334183f);
    p = fmaf(p, x, -0.28768771f);
    return m + p;
}
__device__ __forceinline__ uint32_t smem_u32(const void* p) {
    uint32_t a;
    asm("{ .reg .u64 t; cvta.to.shared.u64 t, %1; cvt.u32.u64 %0, t; }"
        : "=r"(a) : "l"(p));
    return a;
}
__device__ __forceinline__ void mma16(float* c, const uint32_t* a,
                                      uint32_t b0, uint32_t b1) {
    asm volatile(
        "mma.sync.aligned.m16n8k16.row.col.f32.f16.f16.f32 "
        "{%0,%1,%2,%3}, {%4,%5,%6,%7}, {%8,%9}, {%0,%1,%2,%3};"
        : "+f"(c[0]), "+f"(c[1]), "+f"(c[2]), "+f"(c[3])
        : "r"(a[0]), "r"(a[1]), "r"(a[2]), "r"(a[3]), "r"(b0), "r"(b1));
}
__device__ __forceinline__ void ldmat4(uint32_t* r, uint32_t addr) {
    asm volatile(
        "ldmatrix.sync.aligned.m8n8.x4.shared.b16 {%0,%1,%2,%3}, [%4];"
        : "=r"(r[0]), "=r"(r[1]), "=r"(r[2]), "=r"(r[3]) : "r"(addr));
}
__device__ __forceinline__ uint32_t packh2(float lo, float hi) {
    __half2 h = __floats2half2_rn(lo, hi);
    return *reinterpret_cast<uint32_t*>(&h);
}

// ---------------------------------------------------------------------------
// fused prep + in2f
// ---------------------------------------------------------------------------
__global__ void prep_in2f_kernel(const float* __restrict__ x,
                                 const float* __restrict__ Win,
                                 const float* __restrict__ Wf1,
                                 const float* __restrict__ Wf2) {
    if (blockIdx.x < 512) {
        __shared__ float xs[2][NF];
        const int sub = threadIdx.x >> 7;
        const int f = threadIdx.x & 127;
        const int row = blockIdx.x * 2 + sub;
        xs[sub][f] = x[row * NF + f];
        __syncthreads();
        float acc = 0.0f;
#pragma unroll 8
        for (int i = 0; i < NF; ++i) acc += xs[sub][i] * Win[i * NF + f];
        g_y[row * NF + f] = acc;
    } else {
        const int idx = (blockIdx.x - 512) * 256 + threadIdx.x;
        if (idx < 2048) {
            const int ks = idx >> 10, rem = idx & 1023;
            const int lane = rem >> 5, i = rem & 31;
            const int j = i >> 1, r = i & 1;
            const int n = j * 8 + (lane >> 2);
            const int k0 = ks * 16 + r * 8 + (lane & 3) * 2;
            const float v0 = (k0 < NRBF) ? Wf1[k0 * NF + n] : 0.0f;
            const float v1 = (k0 + 1 < NRBF) ? Wf1[(k0 + 1) * NF + n] : 0.0f;
            const int off = (ks * 32 + lane) * 32 +
                            ((((i >> 2) ^ (lane & 7)) << 2) + (i & 3));
            g_w1ph[off] = packh2(v0, v1);
        } else if (idx < 2048 + 8192) {
            const int t = idx - 2048;
            const int ks = t >> 10, rem = t & 1023;
            const int lane = rem >> 5, i = rem & 31;
            const int j = i >> 1, r = i & 1;
            const int n = j * 8 + (lane >> 2);
            const int k0 = ks * 16 + r * 8 + (lane & 3) * 2;
            const int off = (ks * 32 + lane) * 32 +
                            ((((i >> 2) ^ (lane & 7)) << 2) + (i & 3));
            g_w2ph[off] = packh2(Wf2[k0 * NF + n], Wf2[(k0 + 1) * NF + n]);
        }
    }
}

// ---------------------------------------------------------------------------
// SMEM layout (bytes)
// ---------------------------------------------------------------------------
#define OFF_H     0          // 17408 (fp16 H)
#define OFF_W2P   17408      // 32768
#define OFF_RBF   50176      // 5120 (fp16 rbf)
#define OFF_W     55296      // 64*136*4 = 34816 (fp32 W tile; aliased post-loop)
#define OFF_BF1   90112      // 512
#define OFF_BF2   90624      // 512
#define OFF_MASK  91136      // 512
#define OFF_NJ    91648      // 512
#define OFF_NK    92160      // 512
#define SMEM_BYTES 92672     // 90.5KB -> 2 blocks/SM

#define NTHREADS 256

__global__ __launch_bounds__(NTHREADS, 2)
void cfconv_mma(const float* __restrict__ r_ij,
                const float* __restrict__ pmask,
                const float* __restrict__ bf1, const float* __restrict__ bf2,
                const float* __restrict__ Wout, const float* __restrict__ bout,
                const int* __restrict__ nj, const int* __restrict__ nk,
                float* __restrict__ out) {
    extern __shared__ __align__(16) char smem[];
    __half*   sHh   = (__half*)(smem + OFF_H);
    uint32_t* sW2p  = (uint32_t*)(smem + OFF_W2P);
    __half*   sRbfH = (__half*)(smem + OFF_RBF);
    float* sW    = (float*)(smem + OFF_W);
    float* sBf1  = (float*)(smem + OFF_BF1);
    float* sBf2  = (float*)(smem + OFF_BF2);
    float* sMask = (float*)(smem + OFF_MASK);
    int*   sNj   = (int*)(smem + OFF_NJ);
    int*   sNk   = (int*)(smem + OFF_NK);
    float* sPart = (float*)(smem + OFF_W);          // post-loop aliases
    float* sY    = (float*)(smem + OFF_W + 4096);
    float* sRed  = (float*)(smem + OFF_W + 4608);

    const int tid  = threadIdx.x;
    const int wid  = tid >> 5;
    const int lane = tid & 31;
    const int gid  = lane >> 2;
    const int l4   = lane & 3;
    const int wm   = wid >> 2;
    const int wn   = wid & 3;
    const int mbase = wm * 32;
    const int nb4   = wn * 2;
    const int f4    = lane * 4;       // epilogue f-ownership
    const int a = blockIdx.x, b = blockIdx.y;
    const int ba = b * AA + a;
    const float* Yb = g_y + b * AA * NF;

    const int lrow  = (lane & 7) + ((lane >> 3) & 1) * 8;
    const int lkh   = ((lane >> 4) & 1) * 8;
    uint32_t addrR[2], addrH[2];
#pragma unroll
    for (int mt = 0; mt < 2; ++mt) {
        addrR[mt] = smem_u32(sRbfH + (mbase + mt * 16 + lrow) * RSH + lkh);
        addrH[mt] = smem_u32(sHh + (mbase + mt * 16 + lrow) * HSH + lkh);
    }

    // ---- prologue ----
    {
        const uint4* src = (const uint4*)g_w2ph;
        uint4* dst = (uint4*)sW2p;
        for (int i = tid; i < 2048; i += NTHREADS) dst[i] = src[i];
    }
    {
        uint32_t* z = (uint32_t*)sRbfH;
        for (int i = tid; i < (TILT * RSH) / 2; i += NTHREADS) z[i] = 0u;
    }
    if (tid < NF) { sBf1[tid] = bf1[tid]; sBf2[tid] = bf2[tid]; }

    uint32_t w1b[2][8];
#pragma unroll
    for (int ks = 0; ks < 2; ++ks) {
        const uint4* rowp = (const uint4*)g_w1ph + (ks * 32 + lane) * 8;
        uint4 q0 = __ldg(rowp + (nb4 ^ (lane & 7)));
        uint4 q1 = __ldg(rowp + ((nb4 + 1) ^ (lane & 7)));
        w1b[ks][0] = q0.x; w1b[ks][1] = q0.y; w1b[ks][2] = q0.z; w1b[ks][3] = q0.w;
        w1b[ks][4] = q1.x; w1b[ks][5] = q1.y; w1b[ks][6] = q1.z; w1b[ks][7] = q1.w;
    }
    const float4 b2v = *(const float4*)(bf2 + f4);   // epilogue bias, lane-const
    __syncthreads();
    {   // stage tile 0
        const float* rsrc = r_ij + (long)ba * TT * NRBF;
        for (int i = tid; i < TRBF; i += NTHREADS) {
            const int t = i / NRBF, r = i - t * NRBF;
            sRbfH[t * RSH + r] = __float2half_rn(rsrc[i]);
        }
        if (tid < TILT) {
            const long p = (long)ba * TT + tid;
            sMask[tid] = pmask[p];
            sNj[tid] = nj[p];
            sNk[tid] = nk[p];
        }
    }
    __syncthreads();

    float4 accv = make_float4(0.f, 0.f, 0.f, 0.f);

    for (int tile = 0; tile < NTIL; ++tile) {
        const int cur = tile & 1;
        const int nxt = cur ^ 1;

        float C[2][4][4];
#pragma unroll
        for (int mt = 0; mt < 2; ++mt)
#pragma unroll
            for (int j = 0; j < 4; ++j)
#pragma unroll
                for (int q = 0; q < 4; ++q) C[mt][j][q] = 0.0f;

        // ---- GEMM1 ----
#pragma unroll
        for (int ks = 0; ks < 2; ++ks) {
            uint32_t A[2][4];
            ldmat4(A[0], addrR[0] + ks * 32);
            ldmat4(A[1], addrR[1] + ks * 32);
#pragma unroll
            for (int mt = 0; mt < 2; ++mt)
#pragma unroll
                for (int j = 0; j < 4; ++j)
                    mma16(C[mt][j], A[mt], w1b[ks][2 * j], w1b[ks][2 * j + 1]);
        }

        // ---- ssp(C + bf1) -> sH ----
#pragma unroll
        for (int mt = 0; mt < 2; ++mt)
#pragma unroll
            for (int j = 0; j < 4; ++j) {
                const int f0 = wn * 32 + j * 8 + l4 * 2;
                const float2 b1v = *(const float2*)(sBf1 + f0);
                const int r0 = mbase + mt * 16 + gid;
                *(__half2*)(sHh + r0 * HSH + f0) =
                    __floats2half2_rn(ssp(C[mt][j][0] + b1v.x),
                                      ssp(C[mt][j][1] + b1v.y));
                *(__half2*)(sHh + (r0 + 8) * HSH + f0) =
                    __floats2half2_rn(ssp(C[mt][j][2] + b1v.x),
                                      ssp(C[mt][j][3] + b1v.y));
            }

        // ---- prefetch next tile into registers ----
        float rstg[7];
        float stg_mk = 0.0f; int stg_j = 0, stg_k = 0;
        if (tile < NTIL - 1) {
            const float* rnext = r_ij + ((long)ba * TT + (tile + 1) * TILT) * NRBF;
#pragma unroll
            for (int q = 0; q < 7; ++q) {
                const int i = tid + q * NTHREADS;
                if (i < TRBF) rstg[q] = rnext[i];
            }
            if (tid < TILT) {
                const long p = (long)ba * TT + (tile + 1) * TILT + tid;
                stg_mk = pmask[p];
                stg_j = nj[p];
                stg_k = nk[p];
            }
        }
        __syncthreads();   // sync1: sH visible

        // ---- GEMM2 ----
#pragma unroll
        for (int mt = 0; mt < 2; ++mt)
#pragma unroll
            for (int j = 0; j < 4; ++j)
#pragma unroll
                for (int q = 0; q < 4; ++q) C[mt][j][q] = 0.0f;
#pragma unroll
        for (int ks = 0; ks < 8; ++ks) {
            uint32_t A[2][4];
            ldmat4(A[0], addrH[0] + ks * 32);
            ldmat4(A[1], addrH[1] + ks * 32);
            const uint4* rowp = (const uint4*)sW2p + (ks * 32 + lane) * 8;
            uint4 q0 = rowp[nb4 ^ (lane & 7)];
            uint4 q1 = rowp[(nb4 + 1) ^ (lane & 7)];
            uint32_t bu[8] = {q0.x, q0.y, q0.z, q0.w, q1.x, q1.y, q1.z, q1.w};
#pragma unroll
            for (int mt = 0; mt < 2; ++mt)
#pragma unroll
                for (int j = 0; j < 4; ++j)
                    mma16(C[mt][j], A[mt], bu[2 * j], bu[2 * j + 1]);
        }

        // ---- store W fragments -> sW (fp32) ----
#pragma unroll
        for (int mt = 0; mt < 2; ++mt)
#pragma unroll
            for (int rr = 0; rr < 2; ++rr) {
                const int t = mbase + mt * 16 + gid + rr * 8;
#pragma unroll
                for (int j = 0; j < 4; ++j) {
                    const int f0 = wn * 32 + j * 8 + l4 * 2;
                    *(float2*)(sW + t * WS + f0) =
                        make_float2(C[mt][j][rr * 2], C[mt][j][rr * 2 + 1]);
                }
            }
        __syncthreads();   // syncW: sW complete

        // ---- row-coalesced gather epilogue: warp owns 8 t-rows ----
#pragma unroll
        for (int r = 0; r < 8; ++r) {
            const int t = wid * 8 + r;
            const float mk = sMask[cur * TILT + t];
            const float4 yj = *(const float4*)(Yb + sNj[cur * TILT + t] * NF + f4);
            const float4 yk = *(const float4*)(Yb + sNk[cur * TILT + t] * NF + f4);
            const float4 w  = *(const float4*)(sW + t * WS + f4);
            accv.x = fmaf((w.x + b2v.x) * mk, yj.x * yk.x, accv.x);
            accv.y = fmaf((w.y + b2v.y) * mk, yj.y * yk.y, accv.y);
            accv.z = fmaf((w.z + b2v.z) * mk, yj.z * yk.z, accv.z);
            accv.w = fmaf((w.w + b2v.w) * mk, yj.w * yk.w, accv.w);
        }

        // ---- store staged tile ----
        if (tile < NTIL - 1) {
#pragma unroll
            for (int q = 0; q < 7; ++q) {
                const int i = tid + q * NTHREADS;
                if (i < TRBF) {
                    const int t = i / NRBF, r = i - t * NRBF;
                    sRbfH[t * RSH + r] = __float2half_rn(rstg[q]);
                }
            }
            if (tid < TILT) {
                sMask[nxt * TILT + tid] = stg_mk;
                sNj[nxt * TILT + tid] = stg_j;
                sNk[nxt * TILT + tid] = stg_k;
            }
        }
        __syncthreads();   // sync2: sW free, staged data visible
    }

    // ---- cross-warp reduce (warp x f4 partitions are disjoint) ----
    *(float4*)(sPart + wid * NF + f4) = accv;
    __syncthreads();
    if (tid < NF) {
        float s = 0.0f;
#pragma unroll
        for (int w = 0; w < 8; ++w) s += sPart[w * NF + tid];
        sY[tid] = s;
    }
    __syncthreads();

    // ---- f2out ----
    {
        const int o = tid & 127;
        const int q = tid >> 7;
        float s = 0.0f;
        const float* Wp = Wout + q * 64 * NF + o;
#pragma unroll 8
        for (int f = 0; f < 64; ++f) s += sY[q * 64 + f] * Wp[f * NF];
        sRed[q * NF + o] = s;
    }
    __syncthreads();
    if (tid < NF)
        out[(long)ba * NF + tid] = ssp(sRed[tid] + sRed[NF + tid] + bout[tid]);
}

// ---------------------------------------------------------------------------
extern "C" void kernel_launch(void* const* d_in, const int* in_sizes, int n_in,
                              void* d_out, int out_size) {
    const float* x    = (const float*)d_in[0];
    const float* r_ij = (const float*)d_in[1];
    const float* mask = (const float*)d_in[2];
    const float* Wf1  = (const float*)d_in[3];
    const float* bf1  = (const float*)d_in[4];
    const float* Wf2  = (const float*)d_in[5];
    const float* bf2  = (const float*)d_in[6];
    const float* Win  = (const float*)d_in[7];
    const float* Wout = (const float*)d_in[8];
    const float* bout = (const float*)d_in[9];
    const int*   nj   = (const int*)d_in[10];
    const int*   nk   = (const int*)d_in[11];
    float* out = (float*)d_out;

    prep_in2f_kernel<<<552, 256>>>(x, Win, Wf1, Wf2);

    cudaFuncSetAttribute(cfconv_mma,
                         cudaFuncAttributeMaxDynamicSharedMemorySize, SMEM_BYTES);
    dim3 grid(AA, BB);
    cfconv_mma<<<grid, NTHREADS, SMEM_BYTES>>>(r_ij, mask, bf1, bf2,
                                               Wout, bout, nj, nk, out);
}